// round 9
// baseline (speedup 1.0000x reference)
#include <cuda_runtime.h>
#include <stdint.h>

namespace {

constexpr int NQ = 14;
constexpr int NS = 1 << NQ;          // 16384 amplitudes
constexpr int NT = 512;              // threads per CTA

struct Smem {
    float2 st[NS];                    // state, XOR-swizzled layout
    float  pbuf[NS];                  // permuted probabilities
    float2 T[7][4];                   // pair tables: prefix circuit per bit-pair
    float pc[21], ps[21];             // slots 0-6 XX2 (cp col 7+s), 7-20 RX3 (qubit s-7)
    float red[(NT / 32) * NQ];
};

__device__ uint16_t g_inv[NS];       // inverse of the composed MCX permutation

__device__ __forceinline__ float2 cmul(float2 a, float2 b) {
    return make_float2(fmaf(a.x, b.x, -a.y * b.y), fmaf(a.x, b.y, a.y * b.x));
}

// XOR-linear swizzle; bit0 -> addr bit3 ONLY, so (i, i^1) is an aligned 16B block.
// swaddr(a^b) == swaddr(a)^swaddr(b). Conflict-free for all pass lane patterns.
__device__ __host__ __forceinline__ uint32_t swaddr(uint32_t i) {
    return (i << 3) ^ ((i >> 1) & 0x70u);
}

__device__ __forceinline__ float4 ld4(const Smem* sm, uint32_t off) {
    return *reinterpret_cast<const float4*>(reinterpret_cast<const char*>(sm->st) + off);
}
__device__ __forceinline__ void st4(Smem* sm, uint32_t off, float4 v) {
    *reinterpret_cast<float4*>(reinterpret_cast<char*>(sm->st) + off) = v;
}

// Apply NG butterfly gates; gate g pairs t <-> t^combos[g].
template<int G, int NG>
__device__ __forceinline__ void apply_gates(float2 (&a)[1 << G], const int (&combos)[NG],
                                            const float (&cg)[NG], const float (&sg)[NG]) {
#pragma unroll
    for (int g = 0; g < NG; ++g) {
        const int cb = combos[g];
        const int lb = cb & (-cb);
        const float c = cg[g], s = sg[g];
#pragma unroll
        for (int t = 0; t < (1 << G); ++t) {
            if ((t & lb) == 0) {
                const int u = t ^ cb;
                const float2 a0 = a[t], a1 = a[u];
                a[t] = make_float2(fmaf(c, a0.x,  s * a1.y), fmaf(c, a0.y, -s * a1.x));
                a[u] = make_float2(fmaf(c, a1.x,  s * a0.y), fmaf(c, a1.y, -s * a0.x));
            }
        }
    }
}

// Pass A: generate both bit0 sub-orbits from pair tables + XX(9,10),(11,12) + RX q9-12.
__device__ __forceinline__ void run_passA(Smem* sm) {
    constexpr int combos[6] = {1, 4, 2, 3, 8, 12};
    constexpr int slots[6]  = {4, 5, 16, 17, 18, 19};
    float cg[6], sg[6];
#pragma unroll
    for (int g = 0; g < 6; ++g) { cg[g] = sm->pc[slots[g]]; sg[g] = sm->ps[slots[g]]; }

    const int kp = threadIdx.x;                 // exactly 512 orbit-pairs
    const int rep = kp << 5;                    // rep bits 5-13 = kp bits 0-8, bit0 = 0
    const uint32_t abase = swaddr((uint32_t)rep);
    const float2 base = cmul(cmul(sm->T[3][(rep >> 6) & 3], sm->T[4][(rep >> 8) & 3]),
                             cmul(sm->T[5][(rep >> 10) & 3], sm->T[6][(rep >> 12) & 3]));
    const int b5 = (rep >> 5) & 1;
    const float2 q2x[2] = { cmul(base, sm->T[2][2 * b5]),
                            cmul(base, sm->T[2][1 + 2 * b5]) };       // index = bit4
    float2 m8[2][4];
#pragma unroll
    for (int b4 = 0; b4 < 2; ++b4)
#pragma unroll
        for (int j23 = 0; j23 < 4; ++j23)
            m8[b4][j23] = cmul(q2x[b4], sm->T[1][j23]);

    float2 a0[16], a1[16];
#pragma unroll
    for (int t = 0; t < 16; ++t) {
        const int t0 = t & 1, t1 = (t >> 1) & 1, t2 = (t >> 2) & 1, t3 = (t >> 3) & 1;
        const float2 m = m8[t0 ^ t1][(t0 << 1) | (t2 ^ t3)];
        a0[t] = cmul(m, sm->T[0][2 * t2]);       // entry (bit1<<1)|bit0, bit0 = 0
        a1[t] = cmul(m, sm->T[0][2 * t2 + 1]);   // bit0 = 1
    }
    apply_gates<4, 6>(a0, combos, cg, sg);
    apply_gates<4, 6>(a1, combos, cg, sg);
#pragma unroll
    for (int t = 0; t < 16; ++t) {
        uint32_t x = 0;
        if (t & 1) x ^= 0x18u;
        if (t & 2) x ^= 0x10u;
        if (t & 4) x ^= 0x06u;
        if (t & 8) x ^= 0x04u;
        st4(sm, abase ^ swaddr(x), make_float4(a0[t].x, a0[t].y, a1[t].x, a1[t].y));
    }
}

// Pass B: XX(13,0), RX q0, RX q13, XX(7,8), RX q7, RX q8.
// Orbit contains bit0 pairs: i(t)^1 = i(t^3)  (0x2001 ^ 0x2000 = 1).
__device__ __forceinline__ void run_passB(Smem* sm) {
    constexpr int combos[6] = {1, 2, 3, 4, 8, 12};
    constexpr int slots[6]  = {6, 7, 20, 3, 14, 15};
    float cg[6], sg[6];
#pragma unroll
    for (int g = 0; g < 6; ++g) { cg[g] = sm->pc[slots[g]]; sg[g] = sm->ps[slots[g]]; }
#pragma unroll
    for (int it = 0; it < 2; ++it) {
        const int k = threadIdx.x + it * NT;
        const int rep = ((k & 0xF) << 1) | ((k >> 4) << 7);   // bit0 = 0
        const uint32_t abase = swaddr((uint32_t)rep);
        float2 a[16];
#pragma unroll
        for (int t = 0; t < 16; t += 2) {       // even t -> x(t) bit0 = 0
            uint32_t x = 0;
            if (t & 2) x ^= 0x2000u;
            if (t & 4) x ^= 0x60u;
            if (t & 8) x ^= 0x40u;
            const float4 v = ld4(sm, abase ^ swaddr(x));
            a[t]     = make_float2(v.x, v.y);
            a[t ^ 3] = make_float2(v.z, v.w);
        }
        apply_gates<4, 6>(a, combos, cg, sg);
#pragma unroll
        for (int t = 0; t < 16; t += 2) {
            uint32_t x = 0;
            if (t & 2) x ^= 0x2000u;
            if (t & 4) x ^= 0x60u;
            if (t & 8) x ^= 0x40u;
            st4(sm, abase ^ swaddr(x),
                make_float4(a[t].x, a[t].y, a[t ^ 3].x, a[t ^ 3].y));
        }
    }
}

// Pass C: XX(1,2), RX q1,q2, XX(3,4), RX q3,q4 — two bit0 sub-orbits per thread.
__device__ __forceinline__ void run_passC(Smem* sm) {
    constexpr int combos[6] = {1, 2, 3, 4, 8, 12};
    constexpr int slots[6]  = {0, 8, 9, 1, 10, 11};
    float cg[6], sg[6];
#pragma unroll
    for (int g = 0; g < 6; ++g) { cg[g] = sm->pc[slots[g]]; sg[g] = sm->ps[slots[g]]; }
    const int kp = threadIdx.x;                 // 512 pairs, one per thread
    const int rep = ((kp << 1) & 0x1FF) | ((kp >> 8) << 13);   // bit0 = 0
    const uint32_t abase = swaddr((uint32_t)rep);
    float2 a0[16], a1[16];
#pragma unroll
    for (int t = 0; t < 16; ++t) {
        uint32_t x = 0;
        if (t & 1) x ^= 0x1800u;
        if (t & 2) x ^= 0x1000u;
        if (t & 4) x ^= 0x600u;
        if (t & 8) x ^= 0x400u;
        const float4 v = ld4(sm, abase ^ swaddr(x));
        a0[t] = make_float2(v.x, v.y);
        a1[t] = make_float2(v.z, v.w);
    }
    apply_gates<4, 6>(a0, combos, cg, sg);
    apply_gates<4, 6>(a1, combos, cg, sg);
#pragma unroll
    for (int t = 0; t < 16; ++t) {
        uint32_t x = 0;
        if (t & 1) x ^= 0x1800u;
        if (t & 2) x ^= 0x1000u;
        if (t & 4) x ^= 0x600u;
        if (t & 8) x ^= 0x400u;
        st4(sm, abase ^ swaddr(x),
            make_float4(a0[t].x, a0[t].y, a1[t].x, a1[t].y));
    }
}

// Pass D: XX(5,6) + RX q5,q6, scatter |amp|^2 into pbuf at permuted index.
__device__ __forceinline__ void run_passD(Smem* sm) {
    constexpr int combos[3] = {1, 2, 3};
    constexpr int slots[3]  = {2, 12, 13};
    constexpr int XT[4] = {0, 0x180, 0x100, 0x080};
    float cg[3], sg[3];
#pragma unroll
    for (int g = 0; g < 3; ++g) { cg[g] = sm->pc[slots[g]]; sg[g] = sm->ps[slots[g]]; }
#pragma unroll
    for (int it = 0; it < 4; ++it) {
        const int kp = threadIdx.x + it * NT;
        const int rep = ((kp << 1) & 0x7F) | ((kp >> 6) << 9);   // bit0 = 0
        const uint32_t abase = swaddr((uint32_t)rep);
        float2 a0[4], a1[4];
#pragma unroll
        for (int t = 0; t < 4; ++t) {
            const float4 v = ld4(sm, abase ^ swaddr((uint32_t)XT[t]));
            a0[t] = make_float2(v.x, v.y);
            a1[t] = make_float2(v.z, v.w);
        }
        apply_gates<2, 3>(a0, combos, cg, sg);
        apply_gates<2, 3>(a1, combos, cg, sg);
#pragma unroll
        for (int t = 0; t < 4; ++t) {
            const float pr0 = fmaf(a0[t].x, a0[t].x, a0[t].y * a0[t].y);
            const float pr1 = fmaf(a1[t].x, a1[t].x, a1[t].y * a1[t].y);
            sm->pbuf[(int)__ldg(&g_inv[rep ^ XT[t]])]     = pr0;
            sm->pbuf[(int)__ldg(&g_inv[rep ^ XT[t] ^ 1])] = pr1;
        }
    }
}

// Pass E: Walsh-style sign-tree reduction, 32 consecutive probs per thread.
__device__ __forceinline__ void run_passE(Smem* sm, float (&acc)[NQ]) {
    const int tid = threadIdx.x;
    float pv[32];
#pragma unroll
    for (int q = 0; q < 8; ++q) {
        const float4 v = reinterpret_cast<const float4*>(sm->pbuf)[tid * 8 + q];
        pv[4 * q + 0] = v.x; pv[4 * q + 1] = v.y; pv[4 * q + 2] = v.z; pv[4 * q + 3] = v.w;
    }
    float D0 = 0.f, D1 = 0.f, D2 = 0.f, D3 = 0.f;
    float s16[16];
#pragma unroll
    for (int i = 0; i < 16; ++i) { s16[i] = pv[2*i] + pv[2*i+1]; D0 += pv[2*i] - pv[2*i+1]; }
    float s8[8];
#pragma unroll
    for (int i = 0; i < 8; ++i)  { s8[i] = s16[2*i] + s16[2*i+1]; D1 += s16[2*i] - s16[2*i+1]; }
    float s4[4];
#pragma unroll
    for (int i = 0; i < 4; ++i)  { s4[i] = s8[2*i] + s8[2*i+1]; D2 += s8[2*i] - s8[2*i+1]; }
    float s2a[2];
#pragma unroll
    for (int i = 0; i < 2; ++i)  { s2a[i] = s4[2*i] + s4[2*i+1]; D3 += s4[2*i] - s4[2*i+1]; }
    const float S  = s2a[0] + s2a[1];
    const float D4 = s2a[0] - s2a[1];
    acc[13] = D0; acc[12] = D1; acc[11] = D2; acc[10] = D3; acc[9] = D4;
#pragma unroll
    for (int bb = 5; bb <= 13; ++bb)
        acc[13 - bb] = ((tid >> (bb - 5)) & 1) ? -S : S;
}

__global__ void build_inv_kernel() {
    const int i = blockIdx.x * blockDim.x + threadIdx.x;
    int j = i;
#pragma unroll
    for (int w = NQ - 1; w >= 0; --w) {
        const int c1 = NQ - 1 - w;
        const int c2 = NQ - 1 - ((w + 1) % NQ);
        const int tt = NQ - 1 - ((w + 2) % NQ);
        const int b1 = (j >> c1) & 1;
        const int b2 = (j >> c2) & 1;
        if (b1 & (b2 ^ 1)) j ^= (1 << tt);
    }
    g_inv[j] = (uint16_t)i;
}

__global__ __launch_bounds__(NT, 1)
void qsim_kernel(const float* __restrict__ cp, const float* __restrict__ p,
                 float* __restrict__ out) {
    extern __shared__ char smraw[];
    Smem* sm = reinterpret_cast<Smem*>(smraw);
    const int tid = threadIdx.x;
    const int b = blockIdx.x;

    if (tid < NQ) {
        const int w = tid;
        float sn, cs;
        if (w >= 7) {
            sincosf(0.5f * cp[b * NQ + w], &sn, &cs);
            sm->pc[w - 7] = cs; sm->ps[w - 7] = sn;
        }
        sincosf(0.5f * p[(b * 3 + 2) * NQ + w], &sn, &cs);
        sm->pc[7 + w] = cs; sm->ps[7 + w] = sn;
    }
    // Pair tables: T_m for bit-pair (2m+1, 2m) = qubit pair (2k, 2k+1), k = 6-m.
    if (tid < 7) {
        const int m = tid, k = 6 - m;
        const int qa = 2 * k, qb = 2 * k + 1;
        float sa, ca, sb, cb, sx, cx;
        sincosf(0.5f * p[(b * 3 + 0) * NQ + qa], &sa, &ca);
        sincosf(0.5f * p[(b * 3 + 0) * NQ + qb], &sb, &cb);
        sincosf(0.5f * cp[b * NQ + k], &sx, &cx);
        float2 v[4] = { make_float2(ca * cb, 0.f), make_float2(0.f, -ca * sb),
                        make_float2(0.f, -sa * cb), make_float2(-sa * sb, 0.f) };
        float2 u[4];
#pragma unroll
        for (int j = 0; j < 4; ++j) {
            const float2 pv = v[j], qv = v[j ^ 3];
            u[j] = make_float2(fmaf(cx, pv.x,  sx * qv.y), fmaf(cx, pv.y, -sx * qv.x));
        }
        const float tza = p[(b * 3 + 1) * NQ + qa];
        const float tzb = p[(b * 3 + 1) * NQ + qb];
#pragma unroll
        for (int j = 0; j < 4; ++j) {
            const float ang = 0.5f * (((j & 2) ? tza : -tza) + ((j & 1) ? tzb : -tzb));
            float se, ce;
            sincosf(ang, &se, &ce);
            sm->T[m][j] = cmul(u[j], make_float2(ce, se));
        }
    }
    __syncthreads();

    run_passA(sm);
    __syncthreads();
    run_passB(sm);
    __syncthreads();
    run_passC(sm);
    __syncthreads();
    run_passD(sm);
    __syncthreads();

    float acc[NQ];
    run_passE(sm, acc);

#pragma unroll
    for (int w = 0; w < NQ; ++w)
#pragma unroll
        for (int off = 16; off > 0; off >>= 1)
            acc[w] += __shfl_xor_sync(0xffffffffu, acc[w], off);

    const int warp = tid >> 5, lane = tid & 31;
    if (lane == 0) {
#pragma unroll
        for (int w = 0; w < NQ; ++w) sm->red[warp * NQ + w] = acc[w];
    }
    __syncthreads();
    if (tid < NQ) {
        float s = 0.f;
#pragma unroll
        for (int ww = 0; ww < NT / 32; ++ww) s += sm->red[ww * NQ + tid];
        out[b * NQ + tid] = s;
    }
}

} // namespace

extern "C" void kernel_launch(void* const* d_in, const int* in_sizes, int n_in,
                              void* d_out, int out_size) {
    const float* cp = (const float*)d_in[0];
    const float* p  = (const float*)d_in[1];
    float* out = (float*)d_out;
    const int B = in_sizes[0] / NQ;   // 512
    build_inv_kernel<<<NS / NT, NT>>>();
    cudaFuncSetAttribute(qsim_kernel, cudaFuncAttributeMaxDynamicSharedMemorySize,
                         (int)sizeof(Smem));
    qsim_kernel<<<B, NT, sizeof(Smem)>>>(cp, p, out);
}

// round 10
// speedup vs baseline: 1.0991x; 1.0991x over previous
#include <cuda_runtime.h>
#include <stdint.h>

namespace {

constexpr int NQ = 14;
constexpr int NS = 1 << NQ;          // 16384 amplitudes
constexpr int NT = 512;              // threads per CTA

struct Smem {
    float2 st[NS];                    // state, XOR-swizzled layout (no padding)
    float  pbuf[NS];                  // permuted probabilities
    float2 T[7][4];                   // pair tables: prefix circuit per bit-pair
    float pc[21], ps[21];             // slots 0-6 XX2 (cp col 7+s), 7-20 RX3 (qubit s-7)
    float red[(NT / 32) * NQ];
};

// Compile-time inverse of the composed MCX permutation (input-independent).
struct InvTab { uint16_t v[NS]; };
__host__ __device__ constexpr InvTab make_inv() {
    InvTab t{};
    for (int i = 0; i < NS; ++i) {
        int j = i;
        for (int w = NQ - 1; w >= 0; --w) {
            const int c1 = NQ - 1 - w;
            const int c2 = NQ - 1 - ((w + 1) % NQ);
            const int tt = NQ - 1 - ((w + 2) % NQ);
            const int b1 = (j >> c1) & 1;
            const int b2 = (j >> c2) & 1;
            if (b1 & (b2 ^ 1)) j ^= (1 << tt);
        }
        t.v[j] = (uint16_t)i;         // composite(i) = j  =>  inv[j] = i
    }
    return t;
}
__device__ constexpr InvTab g_inv_tab = make_inv();

__device__ __forceinline__ float2 cmul(float2 a, float2 b) {
    return make_float2(fmaf(a.x, b.x, -a.y * b.y), fmaf(a.x, b.y, a.y * b.x));
}

// XOR-linear swizzled byte offset of float2 element i: conflict-free for all passes,
// and swaddr(a^b) == swaddr(a) ^ swaddr(b)  -> orbit addresses = base ^ const.
__device__ __host__ __forceinline__ uint32_t swaddr(uint32_t i) {
    return (i << 3) ^ ((i >> 1) & 0x78u);
}

__device__ __forceinline__ float2 ld_st(const Smem* sm, uint32_t off) {
    return *reinterpret_cast<const float2*>(reinterpret_cast<const char*>(sm->st) + off);
}
__device__ __forceinline__ void st_st(Smem* sm, uint32_t off, float2 v) {
    *reinterpret_cast<float2*>(reinterpret_cast<char*>(sm->st) + off) = v;
}

// Apply NG butterfly gates; gate g pairs t <-> t^combos[g] (combo = mask over gen dims).
template<int G, int NG>
__device__ __forceinline__ void apply_gates(float2 (&a)[1 << G], const int (&combos)[NG],
                                            const float (&cg)[NG], const float (&sg)[NG]) {
#pragma unroll
    for (int g = 0; g < NG; ++g) {
        const int cb = combos[g];
        const int lb = cb & (-cb);
        const float c = cg[g], s = sg[g];
#pragma unroll
        for (int t = 0; t < (1 << G); ++t) {
            if ((t & lb) == 0) {
                const int u = t ^ cb;
                const float2 a0 = a[t], a1 = a[u];
                a[t] = make_float2(fmaf(c, a0.x,  s * a1.y), fmaf(c, a0.y, -s * a1.x));
                a[u] = make_float2(fmaf(c, a1.x,  s * a0.y), fmaf(c, a1.y, -s * a0.x));
            }
        }
    }
}

// rep formulas as functor structs (no --extended-lambda available)
struct RepB { __device__ __forceinline__ int operator()(int k) const {
    return ((k & 0xF) << 1) | ((k >> 4) << 7);   // non-span bits 1-4, 7-12
}};
struct RepC { __device__ __forceinline__ int operator()(int k) const {
    return (k & 0x1FF) | ((k >> 9) << 13);       // non-span bits 0-8, 13
}};

// Generic load-gates-store pass with caller-provided rep formula (RepF).
template<int G, int NG, class RepF>
__device__ __forceinline__ void run_pass(Smem* sm, RepF repf, const int (&gens)[G],
                                         const int (&combos)[NG], const int (&slots)[NG]) {
    constexpr int NO = 1 << G;
    float cg[NG], sg[NG];
#pragma unroll
    for (int g = 0; g < NG; ++g) { cg[g] = sm->pc[slots[g]]; sg[g] = sm->ps[slots[g]]; }
    for (int k = threadIdx.x; k < (NS >> G); k += NT) {
        const uint32_t abase = swaddr((uint32_t)repf(k));
        uint32_t aoff[NO];
#pragma unroll
        for (int t = 0; t < NO; ++t) {
            uint32_t x = 0;
#pragma unroll
            for (int g = 0; g < G; ++g) if ((t >> g) & 1) x ^= (uint32_t)gens[g];
            aoff[t] = abase ^ swaddr(x);   // swaddr(x) folds to a constant
        }
        float2 a[NO];
#pragma unroll
        for (int t = 0; t < NO; ++t) a[t] = ld_st(sm, aoff[t]);
        apply_gates<G, NG>(a, combos, cg, sg);
#pragma unroll
        for (int t = 0; t < NO; ++t) st_st(sm, aoff[t], a[t]);
    }
}

// Pass A: generate state from pair tables + XX(9,10), XX(11,12), RX q9..q12.
__device__ __forceinline__ void run_passA(Smem* sm) {
    // gens: g0=0x18(t0), g1=0x10(t1), g2=0x06(t2), g3=0x04(t3); span bits 1-4
    constexpr int combos[6] = {1, 4, 2, 3, 8, 12};  // XX(9,10),XX(11,12),RX q9,q10,q11,q12
    constexpr int slots[6]  = {4, 5, 16, 17, 18, 19};
    float cg[6], sg[6];
#pragma unroll
    for (int g = 0; g < 6; ++g) { cg[g] = sm->pc[slots[g]]; sg[g] = sm->ps[slots[g]]; }

    for (int k = threadIdx.x; k < (NS >> 4); k += NT) {
        const int rep = (k & 1) | ((k >> 1) << 5);          // non-span bits 0, 5-13
        const uint32_t abase = swaddr((uint32_t)rep);
        // amp(i) = prod_m T_m[(i>>2m)&3]; bits 5-13 fixed by rep
        const float2 base = cmul(cmul(sm->T[3][(rep >> 6) & 3], sm->T[4][(rep >> 8) & 3]),
                                 cmul(sm->T[5][(rep >> 10) & 3], sm->T[6][(rep >> 12) & 3]));
        const int b0 = rep & 1, b5 = (rep >> 5) & 1;
        const float2 q2x[2] = { cmul(base, sm->T[2][2 * b5]),
                                cmul(base, sm->T[2][1 + 2 * b5]) };   // index = bit4
        const float2 q0[2] = { sm->T[0][b0], sm->T[0][b0 + 2] };      // index = bit1
        float2 m8[2][4];
#pragma unroll
        for (int b4 = 0; b4 < 2; ++b4)
#pragma unroll
            for (int j23 = 0; j23 < 4; ++j23)
                m8[b4][j23] = cmul(q2x[b4], sm->T[1][j23]);
        float2 a[16];
#pragma unroll
        for (int t = 0; t < 16; ++t) {
            // in-span bits as functions of t: b1=t2, b2=t2^t3, b3=t0, b4=t0^t1
            const int t0 = t & 1, t1 = (t >> 1) & 1, t2 = (t >> 2) & 1, t3 = (t >> 3) & 1;
            a[t] = cmul(m8[t0 ^ t1][(t0 << 1) | (t2 ^ t3)], q0[t2]);
        }
        apply_gates<4, 6>(a, combos, cg, sg);
#pragma unroll
        for (int t = 0; t < 16; ++t) {
            uint32_t x = 0;
            if (t & 1) x ^= 0x18u;
            if (t & 2) x ^= 0x10u;
            if (t & 4) x ^= 0x06u;
            if (t & 8) x ^= 0x04u;
            st_st(sm, abase ^ swaddr(x), a[t]);
        }
    }
}

// Pass D: XX(5,6) + RX q5,q6, then scatter |amp|^2 into pbuf at permuted index.
__device__ __forceinline__ void run_passD(Smem* sm) {
    constexpr int combos[3] = {1, 2, 3};            // XX(5,6), RX q5, RX q6
    constexpr int slots[3]  = {2, 12, 13};
    constexpr int XT[4] = {0, 0x180, 0x100, 0x080};
    float cg[3], sg[3];
#pragma unroll
    for (int g = 0; g < 3; ++g) { cg[g] = sm->pc[slots[g]]; sg[g] = sm->ps[slots[g]]; }
    for (int k = threadIdx.x; k < (NS >> 2); k += NT) {
        const int rep = (k & 0x7F) | ((k >> 7) << 9);  // non-span bits 0-6, 9-13
        const uint32_t abase = swaddr((uint32_t)rep);
        float2 a[4];
#pragma unroll
        for (int t = 0; t < 4; ++t) a[t] = ld_st(sm, abase ^ swaddr((uint32_t)XT[t]));
        apply_gates<2, 3>(a, combos, cg, sg);
#pragma unroll
        for (int t = 0; t < 4; ++t) {
            const float pr = fmaf(a[t].x, a[t].x, a[t].y * a[t].y);
            const int i = (int)g_inv_tab.v[rep ^ XT[t]];
            sm->pbuf[i] = pr;
        }
    }
}

// Pass E: Walsh-style sign-tree reduction over natural-order probabilities.
__device__ __forceinline__ void run_passE(Smem* sm, float (&acc)[NQ]) {
    const int tid = threadIdx.x;
    float pv[32];
#pragma unroll
    for (int q = 0; q < 8; ++q) {
        const float4 v = reinterpret_cast<const float4*>(sm->pbuf)[tid * 8 + q];
        pv[4 * q + 0] = v.x; pv[4 * q + 1] = v.y; pv[4 * q + 2] = v.z; pv[4 * q + 3] = v.w;
    }
    float D0 = 0.f, D1 = 0.f, D2 = 0.f, D3 = 0.f;
    float s16[16];
#pragma unroll
    for (int i = 0; i < 16; ++i) { s16[i] = pv[2*i] + pv[2*i+1]; D0 += pv[2*i] - pv[2*i+1]; }
    float s8[8];
#pragma unroll
    for (int i = 0; i < 8; ++i)  { s8[i] = s16[2*i] + s16[2*i+1]; D1 += s16[2*i] - s16[2*i+1]; }
    float s4[4];
#pragma unroll
    for (int i = 0; i < 4; ++i)  { s4[i] = s8[2*i] + s8[2*i+1]; D2 += s8[2*i] - s8[2*i+1]; }
    float s2a[2];
#pragma unroll
    for (int i = 0; i < 2; ++i)  { s2a[i] = s4[2*i] + s4[2*i+1]; D3 += s4[2*i] - s4[2*i+1]; }
    const float S  = s2a[0] + s2a[1];
    const float D4 = s2a[0] - s2a[1];
    acc[13] = D0; acc[12] = D1; acc[11] = D2; acc[10] = D3; acc[9] = D4;
    // bits 5..13 of index j = tid bits 0..8; qubit w = 13 - b
#pragma unroll
    for (int bb = 5; bb <= 13; ++bb)
        acc[13 - bb] = ((tid >> (bb - 5)) & 1) ? -S : S;
}

__global__ __launch_bounds__(NT, 1)
void qsim_kernel(const float* __restrict__ cp, const float* __restrict__ p,
                 float* __restrict__ out) {
    extern __shared__ char smraw[];
    Smem* sm = reinterpret_cast<Smem*>(smraw);
    const int tid = threadIdx.x;
    const int b = blockIdx.x;

    if (tid < NQ) {
        const int w = tid;
        float sn, cs;
        if (w >= 7) {
            sincosf(0.5f * cp[b * NQ + w], &sn, &cs);
            sm->pc[w - 7] = cs; sm->ps[w - 7] = sn;
        }
        sincosf(0.5f * p[(b * 3 + 2) * NQ + w], &sn, &cs);
        sm->pc[7 + w] = cs; sm->ps[7 + w] = sn;
    }
    // Pair tables: T_m for bit-pair (2m+1, 2m) = qubit pair (2k, 2k+1), k = 6-m.
    if (tid < 7) {
        const int m = tid, k = 6 - m;
        const int qa = 2 * k, qb = 2 * k + 1;
        float sa, ca, sb, cb, sx, cx;
        sincosf(0.5f * p[(b * 3 + 0) * NQ + qa], &sa, &ca);
        sincosf(0.5f * p[(b * 3 + 0) * NQ + qb], &sb, &cb);
        sincosf(0.5f * cp[b * NQ + k], &sx, &cx);
        float2 v[4] = { make_float2(ca * cb, 0.f), make_float2(0.f, -ca * sb),
                        make_float2(0.f, -sa * cb), make_float2(-sa * sb, 0.f) };
        float2 u[4];
#pragma unroll
        for (int j = 0; j < 4; ++j) {
            const float2 pv = v[j], qv = v[j ^ 3];
            u[j] = make_float2(fmaf(cx, pv.x,  sx * qv.y), fmaf(cx, pv.y, -sx * qv.x));
        }
        const float tza = p[(b * 3 + 1) * NQ + qa];
        const float tzb = p[(b * 3 + 1) * NQ + qb];
#pragma unroll
        for (int j = 0; j < 4; ++j) {
            const float ang = 0.5f * (((j & 2) ? tza : -tza) + ((j & 1) ? tzb : -tzb));
            float se, ce;
            sincosf(ang, &se, &ce);
            sm->T[m][j] = cmul(u[j], make_float2(ce, se));
        }
    }
    __syncthreads();

    run_passA(sm);                                   // generate + XX(9,10),(11,12) + RX q9-12
    __syncthreads();

    {   // Pass B: XX(13,0), RX q0,q13, XX(7,8), RX q7,q8
        constexpr int gens[4] = {0x2001, 0x2000, 0x60, 0x40};
        constexpr int combos[6] = {1, 2, 3, 4, 8, 12};
        constexpr int slots[6]  = {6, 7, 20, 3, 14, 15};
        run_pass<4, 6>(sm, RepB{}, gens, combos, slots);
    }
    __syncthreads();

    {   // Pass C: XX(1,2), RX q1,q2, XX(3,4), RX q3,q4
        constexpr int gens[4] = {0x1800, 0x1000, 0x600, 0x400};
        constexpr int combos[6] = {1, 2, 3, 4, 8, 12};
        constexpr int slots[6]  = {0, 8, 9, 1, 10, 11};
        run_pass<4, 6>(sm, RepC{}, gens, combos, slots);
    }
    __syncthreads();

    run_passD(sm);                                   // XX(5,6)+RX q5,q6 + prob scatter
    __syncthreads();

    float acc[NQ];
    run_passE(sm, acc);                              // sign-tree reduction

#pragma unroll
    for (int w = 0; w < NQ; ++w)
#pragma unroll
        for (int off = 16; off > 0; off >>= 1)
            acc[w] += __shfl_xor_sync(0xffffffffu, acc[w], off);

    const int warp = tid >> 5, lane = tid & 31;
    if (lane == 0) {
#pragma unroll
        for (int w = 0; w < NQ; ++w) sm->red[warp * NQ + w] = acc[w];
    }
    __syncthreads();
    if (tid < NQ) {
        float s = 0.f;
#pragma unroll
        for (int ww = 0; ww < NT / 32; ++ww) s += sm->red[ww * NQ + tid];
        out[b * NQ + tid] = s;
    }
}

} // namespace

extern "C" void kernel_launch(void* const* d_in, const int* in_sizes, int n_in,
                              void* d_out, int out_size) {
    const float* cp = (const float*)d_in[0];
    const float* p  = (const float*)d_in[1];
    float* out = (float*)d_out;
    const int B = in_sizes[0] / NQ;   // 512
    cudaFuncSetAttribute(qsim_kernel, cudaFuncAttributeMaxDynamicSharedMemorySize,
                         (int)sizeof(Smem));
    qsim_kernel<<<B, NT, sizeof(Smem)>>>(cp, p, out);
}

// round 11
// speedup vs baseline: 1.1009x; 1.0016x over previous
#include <cuda_runtime.h>
#include <stdint.h>

namespace {
typedef unsigned long long u64;

constexpr int NQ = 14;
constexpr int NS = 1 << NQ;          // 16384 amplitudes
constexpr int NT = 512;              // threads per CTA

struct Smem {
    float2 st[NS];                    // state, XOR-swizzled; (i,i^1) share a 16B block
    float  pbuf[NS];                  // permuted probabilities
    float2 T[7][4];                   // pair tables: prefix circuit per bit-pair
    float pc[21], ps[21];             // slots 0-6 XX2 (cp col 7+s), 7-20 RX3 (qubit s-7)
    float red[(NT / 32) * NQ];
};

// Compile-time inverse of the composed MCX permutation (input-independent).
struct InvTab { uint16_t v[NS]; };
__host__ __device__ constexpr InvTab make_inv() {
    InvTab t{};
    for (int i = 0; i < NS; ++i) {
        int j = i;
        for (int w = NQ - 1; w >= 0; --w) {
            const int c1 = NQ - 1 - w;
            const int c2 = NQ - 1 - ((w + 1) % NQ);
            const int tt = NQ - 1 - ((w + 2) % NQ);
            const int b1 = (j >> c1) & 1;
            const int b2 = (j >> c2) & 1;
            if (b1 & (b2 ^ 1)) j ^= (1 << tt);
        }
        t.v[j] = (uint16_t)i;
    }
    return t;
}
__device__ constexpr InvTab g_inv_tab = make_inv();

// ---- packed f32x2 helpers (FFMA2 path; only reachable via PTX) ----
__device__ __forceinline__ u64 pack2(float lo, float hi) {
    u64 r; asm("mov.b64 %0, {%1, %2};" : "=l"(r) : "f"(lo), "f"(hi)); return r;
}
__device__ __forceinline__ void unpack2(u64 v, float& lo, float& hi) {
    asm("mov.b64 {%0, %1}, %2;" : "=f"(lo), "=f"(hi) : "l"(v));
}
__device__ __forceinline__ u64 bcast2(float x) { return pack2(x, x); }
__device__ __forceinline__ u64 swap2(u64 v) {
    float a, b; unpack2(v, a, b); return pack2(b, a);
}
__device__ __forceinline__ u64 fma2(u64 a, u64 b, u64 c) {
    u64 d; asm("fma.rn.f32x2 %0, %1, %2, %3;" : "=l"(d) : "l"(a), "l"(b), "l"(c)); return d;
}
__device__ __forceinline__ u64 mul2(u64 a, u64 b) {
    u64 d; asm("mul.rn.f32x2 %0, %1, %2;" : "=l"(d) : "l"(a), "l"(b)); return d;
}

__device__ __forceinline__ float2 cmul(float2 a, float2 b) {
    return make_float2(fmaf(a.x, b.x, -a.y * b.y), fmaf(a.x, b.y, a.y * b.x));
}

// XOR-linear swizzle; index bit0 -> addr bit3 ONLY, so (i, i^1) is one aligned 16B block.
__device__ __host__ __forceinline__ uint32_t swaddr(uint32_t i) {
    return (i << 3) ^ ((i >> 1) & 0x70u);
}
__device__ __forceinline__ float4 ld4(const Smem* sm, uint32_t off) {
    return *reinterpret_cast<const float4*>(reinterpret_cast<const char*>(sm->st) + off);
}
__device__ __forceinline__ void st4(Smem* sm, uint32_t off, float4 v) {
    *reinterpret_cast<float4*>(reinterpret_cast<char*>(sm->st) + off) = v;
}
// load/store a packed bit0-pair: block = [re0 im0 re1 im1]
__device__ __forceinline__ void ld2(const Smem* sm, uint32_t off, u64& R, u64& I) {
    const float4 v = ld4(sm, off);
    R = pack2(v.x, v.z); I = pack2(v.y, v.w);
}
__device__ __forceinline__ void st2(Smem* sm, uint32_t off, u64 R, u64 I) {
    float r0, r1, i0, i1; unpack2(R, r0, r1); unpack2(I, i0, i1);
    st4(sm, off, make_float4(r0, i0, r1, i1));
}

// Lane-uniform packed butterfly gates (gate dims exclude bit0).
template<int G, int NG>
__device__ __forceinline__ void apply_gates2(u64 (&Re)[1 << G], u64 (&Im)[1 << G],
                                             const int (&combos)[NG],
                                             const float (&cg)[NG], const float (&sg)[NG]) {
#pragma unroll
    for (int g = 0; g < NG; ++g) {
        const int cb = combos[g], lb = cb & (-cb);
        const u64 cP = bcast2(cg[g]), sP = bcast2(sg[g]), nsP = bcast2(-sg[g]);
#pragma unroll
        for (int t = 0; t < (1 << G); ++t) {
            if ((t & lb) == 0) {
                const int u = t ^ cb;
                const u64 r0 = fma2(cP, Re[t], mul2(sP,  Im[u]));
                const u64 i0 = fma2(cP, Im[t], mul2(nsP, Re[u]));
                const u64 r1 = fma2(cP, Re[u], mul2(sP,  Im[t]));
                const u64 i1 = fma2(cP, Im[u], mul2(nsP, Re[t]));
                Re[t] = r0; Im[t] = i0; Re[u] = r1; Im[u] = i1;
            }
        }
    }
}

// Pass A: generate packed state from pair tables + XX(9,10),(11,12) + RX q9-12.
__device__ __forceinline__ void run_passA(Smem* sm) {
    constexpr int combos[6] = {1, 4, 2, 3, 8, 12};
    constexpr int slots[6]  = {4, 5, 16, 17, 18, 19};
    float cg[6], sg[6];
#pragma unroll
    for (int g = 0; g < 6; ++g) { cg[g] = sm->pc[slots[g]]; sg[g] = sm->ps[slots[g]]; }

    const int tid = threadIdx.x;                // exactly 512 orbit-pairs
    const int rep = tid << 5;                   // bits 5-13 = tid bits 0-8; bit0 = 0
    const uint32_t abase = swaddr((uint32_t)rep);
    const float2 base = cmul(cmul(sm->T[3][(rep >> 6) & 3], sm->T[4][(rep >> 8) & 3]),
                             cmul(sm->T[5][(rep >> 10) & 3], sm->T[6][(rep >> 12) & 3]));
    const int b5 = tid & 1;
    const float2 q2x[2] = { cmul(base, sm->T[2][2 * b5]),
                            cmul(base, sm->T[2][1 + 2 * b5]) };      // index = bit4
    float2 m8[2][4];
#pragma unroll
    for (int b4 = 0; b4 < 2; ++b4)
#pragma unroll
        for (int j23 = 0; j23 < 4; ++j23)
            m8[b4][j23] = cmul(q2x[b4], sm->T[1][j23]);
    // packed T0 lanes: lane0 = bit0=0 entry, lane1 = bit0=1 entry
    u64 T0re[2], T0im[2];
#pragma unroll
    for (int b1 = 0; b1 < 2; ++b1) {
        T0re[b1] = pack2(sm->T[0][2 * b1].x, sm->T[0][2 * b1 + 1].x);
        T0im[b1] = pack2(sm->T[0][2 * b1].y, sm->T[0][2 * b1 + 1].y);
    }
    u64 Re[16], Im[16];
#pragma unroll
    for (int t = 0; t < 16; ++t) {
        const int t0 = t & 1, t1 = (t >> 1) & 1, t2 = (t >> 2) & 1, t3 = (t >> 3) & 1;
        const float2 m = m8[t0 ^ t1][(t0 << 1) | (t2 ^ t3)];
        const u64 mx = bcast2(m.x), my = bcast2(m.y), nmy = bcast2(-m.y);
        Re[t] = fma2(mx, T0re[t2], mul2(nmy, T0im[t2]));
        Im[t] = fma2(mx, T0im[t2], mul2(my,  T0re[t2]));
    }
    apply_gates2<4, 6>(Re, Im, combos, cg, sg);
#pragma unroll
    for (int t = 0; t < 16; ++t) {
        uint32_t x = 0;
        if (t & 1) x ^= 0x18u;
        if (t & 2) x ^= 0x10u;
        if (t & 4) x ^= 0x06u;
        if (t & 8) x ^= 0x04u;
        st2(sm, abase ^ swaddr(x), Re[t], Im[t]);
    }
}

// Pass B: XX(13,0), RX q0, RX q13 (bit0-involved -> lane swaps), XX(7,8), RX q7, RX q8.
__device__ __forceinline__ void run_passB(Smem* sm) {
    const float c1 = sm->pc[6],  s1 = sm->ps[6];    // XX(13,0)
    const float c2 = sm->pc[7],  s2 = sm->ps[7];    // RX q0  (bit13)
    const float c3 = sm->pc[20], s3 = sm->ps[20];   // RX q13 (bit0)
    constexpr int combosU[3] = {2, 4, 6};           // XX(7,8), RX q7, RX q8
    constexpr int slotsU[3]  = {3, 14, 15};
    float cgU[3], sgU[3];
#pragma unroll
    for (int g = 0; g < 3; ++g) { cgU[g] = sm->pc[slotsU[g]]; sgU[g] = sm->ps[slotsU[g]]; }
#pragma unroll
    for (int it = 0; it < 2; ++it) {
        const int k = threadIdx.x + it * NT;
        const int rep = ((k & 0xF) << 1) | ((k >> 4) << 7);   // bit0 = 0
        const uint32_t abase = swaddr((uint32_t)rep);
        u64 Re[8], Im[8];                            // dims: t0=0x2000, t1=0x60, t2=0x40
#pragma unroll
        for (int t = 0; t < 8; ++t) {
            uint32_t x = 0;
            if (t & 1) x ^= 0x2000u;
            if (t & 2) x ^= 0x60u;
            if (t & 4) x ^= 0x40u;
            ld2(sm, abase ^ swaddr(x), Re[t], Im[t]);
        }
        {   // XX(13,0): pairs (t, t^1[dim 0x2000]) with cross-lane partner
            const u64 cP = bcast2(c1), sP = bcast2(s1), nsP = bcast2(-s1);
#pragma unroll
            for (int t = 0; t < 8; t += 2) {
                const int u = t + 1;
                const u64 sIu = swap2(Im[u]), sRu = swap2(Re[u]);
                const u64 sIt = swap2(Im[t]), sRt = swap2(Re[t]);
                const u64 r0 = fma2(cP, Re[t], mul2(sP,  sIu));
                const u64 i0 = fma2(cP, Im[t], mul2(nsP, sRu));
                const u64 r1 = fma2(cP, Re[u], mul2(sP,  sIt));
                const u64 i1 = fma2(cP, Im[u], mul2(nsP, sRt));
                Re[t] = r0; Im[t] = i0; Re[u] = r1; Im[u] = i1;
            }
        }
        {   // RX q0 (bit13): lane-uniform pairs (t, t^1)
            const u64 cP = bcast2(c2), sP = bcast2(s2), nsP = bcast2(-s2);
#pragma unroll
            for (int t = 0; t < 8; t += 2) {
                const int u = t + 1;
                const u64 r0 = fma2(cP, Re[t], mul2(sP,  Im[u]));
                const u64 i0 = fma2(cP, Im[t], mul2(nsP, Re[u]));
                const u64 r1 = fma2(cP, Re[u], mul2(sP,  Im[t]));
                const u64 i1 = fma2(cP, Im[u], mul2(nsP, Re[t]));
                Re[t] = r0; Im[t] = i0; Re[u] = r1; Im[u] = i1;
            }
        }
        {   // RX q13 (bit0): within-element lane butterfly
            const u64 cP = bcast2(c3), sP = bcast2(s3), nsP = bcast2(-s3);
#pragma unroll
            for (int t = 0; t < 8; ++t) {
                const u64 sI = swap2(Im[t]), sR = swap2(Re[t]);
                const u64 r = fma2(cP, Re[t], mul2(sP,  sI));
                const u64 i = fma2(cP, Im[t], mul2(nsP, sR));
                Re[t] = r; Im[t] = i;
            }
        }
        apply_gates2<3, 3>(Re, Im, combosU, cgU, sgU);
#pragma unroll
        for (int t = 0; t < 8; ++t) {
            uint32_t x = 0;
            if (t & 1) x ^= 0x2000u;
            if (t & 2) x ^= 0x60u;
            if (t & 4) x ^= 0x40u;
            st2(sm, abase ^ swaddr(x), Re[t], Im[t]);
        }
    }
}

// Pass C: XX(1,2), RX q1,q2, XX(3,4), RX q3,q4 — fully lane-uniform.
__device__ __forceinline__ void run_passC(Smem* sm) {
    constexpr int combos[6] = {1, 2, 3, 4, 8, 12};
    constexpr int slots[6]  = {0, 8, 9, 1, 10, 11};
    float cg[6], sg[6];
#pragma unroll
    for (int g = 0; g < 6; ++g) { cg[g] = sm->pc[slots[g]]; sg[g] = sm->ps[slots[g]]; }
    const int tid = threadIdx.x;                   // 512 orbit-pairs
    const int rep = ((tid << 1) & 0x1FF) | ((tid >> 8) << 13);   // bit0 = 0
    const uint32_t abase = swaddr((uint32_t)rep);
    u64 Re[16], Im[16];
#pragma unroll
    for (int t = 0; t < 16; ++t) {
        uint32_t x = 0;
        if (t & 1) x ^= 0x1800u;
        if (t & 2) x ^= 0x1000u;
        if (t & 4) x ^= 0x600u;
        if (t & 8) x ^= 0x400u;
        ld2(sm, abase ^ swaddr(x), Re[t], Im[t]);
    }
    apply_gates2<4, 6>(Re, Im, combos, cg, sg);
#pragma unroll
    for (int t = 0; t < 16; ++t) {
        uint32_t x = 0;
        if (t & 1) x ^= 0x1800u;
        if (t & 2) x ^= 0x1000u;
        if (t & 4) x ^= 0x600u;
        if (t & 8) x ^= 0x400u;
        st2(sm, abase ^ swaddr(x), Re[t], Im[t]);
    }
}

// Pass D: XX(5,6) + RX q5,q6 (lane-uniform) + packed |amp|^2 + permuted scatter.
__device__ __forceinline__ void run_passD(Smem* sm) {
    constexpr int combos[3] = {1, 2, 3};
    constexpr int slots[3]  = {2, 12, 13};
    constexpr int XT[4] = {0, 0x180, 0x100, 0x080};
    float cg[3], sg[3];
#pragma unroll
    for (int g = 0; g < 3; ++g) { cg[g] = sm->pc[slots[g]]; sg[g] = sm->ps[slots[g]]; }
#pragma unroll
    for (int it = 0; it < 4; ++it) {
        const int kp = threadIdx.x + it * NT;
        const int rep = ((kp << 1) & 0x7F) | ((kp >> 6) << 9);   // bit0 = 0
        const uint32_t abase = swaddr((uint32_t)rep);
        u64 Re[4], Im[4];
#pragma unroll
        for (int t = 0; t < 4; ++t) ld2(sm, abase ^ swaddr((uint32_t)XT[t]), Re[t], Im[t]);
        apply_gates2<2, 3>(Re, Im, combos, cg, sg);
#pragma unroll
        for (int t = 0; t < 4; ++t) {
            const u64 prP = fma2(Re[t], Re[t], mul2(Im[t], Im[t]));
            float p0, p1; unpack2(prP, p0, p1);
            sm->pbuf[(int)g_inv_tab.v[rep ^ XT[t]]]     = p0;
            sm->pbuf[(int)g_inv_tab.v[rep ^ XT[t] ^ 1]] = p1;
        }
    }
}

// Pass E: Walsh-style sign-tree reduction over natural-order probabilities.
__device__ __forceinline__ void run_passE(Smem* sm, float (&acc)[NQ]) {
    const int tid = threadIdx.x;
    float pv[32];
#pragma unroll
    for (int q = 0; q < 8; ++q) {
        const float4 v = reinterpret_cast<const float4*>(sm->pbuf)[tid * 8 + q];
        pv[4 * q + 0] = v.x; pv[4 * q + 1] = v.y; pv[4 * q + 2] = v.z; pv[4 * q + 3] = v.w;
    }
    float D0 = 0.f, D1 = 0.f, D2 = 0.f, D3 = 0.f;
    float s16[16];
#pragma unroll
    for (int i = 0; i < 16; ++i) { s16[i] = pv[2*i] + pv[2*i+1]; D0 += pv[2*i] - pv[2*i+1]; }
    float s8[8];
#pragma unroll
    for (int i = 0; i < 8; ++i)  { s8[i] = s16[2*i] + s16[2*i+1]; D1 += s16[2*i] - s16[2*i+1]; }
    float s4[4];
#pragma unroll
    for (int i = 0; i < 4; ++i)  { s4[i] = s8[2*i] + s8[2*i+1]; D2 += s8[2*i] - s8[2*i+1]; }
    float s2a[2];
#pragma unroll
    for (int i = 0; i < 2; ++i)  { s2a[i] = s4[2*i] + s4[2*i+1]; D3 += s4[2*i] - s4[2*i+1]; }
    const float S  = s2a[0] + s2a[1];
    const float D4 = s2a[0] - s2a[1];
    acc[13] = D0; acc[12] = D1; acc[11] = D2; acc[10] = D3; acc[9] = D4;
#pragma unroll
    for (int bb = 5; bb <= 13; ++bb)
        acc[13 - bb] = ((tid >> (bb - 5)) & 1) ? -S : S;
}

__global__ __launch_bounds__(NT, 1)
void qsim_kernel(const float* __restrict__ cp, const float* __restrict__ p,
                 float* __restrict__ out) {
    extern __shared__ char smraw[];
    Smem* sm = reinterpret_cast<Smem*>(smraw);
    const int tid = threadIdx.x;
    const int b = blockIdx.x;

    if (tid < NQ) {
        const int w = tid;
        float sn, cs;
        if (w >= 7) {
            sincosf(0.5f * cp[b * NQ + w], &sn, &cs);
            sm->pc[w - 7] = cs; sm->ps[w - 7] = sn;
        }
        sincosf(0.5f * p[(b * 3 + 2) * NQ + w], &sn, &cs);
        sm->pc[7 + w] = cs; sm->ps[7 + w] = sn;
    }
    // Pair tables: T_m for bit-pair (2m+1, 2m) = qubit pair (2k, 2k+1), k = 6-m.
    if (tid < 7) {
        const int m = tid, k = 6 - m;
        const int qa = 2 * k, qb = 2 * k + 1;
        float sa, ca, sb, cb, sx, cx;
        sincosf(0.5f * p[(b * 3 + 0) * NQ + qa], &sa, &ca);
        sincosf(0.5f * p[(b * 3 + 0) * NQ + qb], &sb, &cb);
        sincosf(0.5f * cp[b * NQ + k], &sx, &cx);
        float2 v[4] = { make_float2(ca * cb, 0.f), make_float2(0.f, -ca * sb),
                        make_float2(0.f, -sa * cb), make_float2(-sa * sb, 0.f) };
        float2 u[4];
#pragma unroll
        for (int j = 0; j < 4; ++j) {
            const float2 pv = v[j], qv = v[j ^ 3];
            u[j] = make_float2(fmaf(cx, pv.x,  sx * qv.y), fmaf(cx, pv.y, -sx * qv.x));
        }
        const float tza = p[(b * 3 + 1) * NQ + qa];
        const float tzb = p[(b * 3 + 1) * NQ + qb];
#pragma unroll
        for (int j = 0; j < 4; ++j) {
            const float ang = 0.5f * (((j & 2) ? tza : -tza) + ((j & 1) ? tzb : -tzb));
            float se, ce;
            sincosf(ang, &se, &ce);
            sm->T[m][j] = cmul(u[j], make_float2(ce, se));
        }
    }
    __syncthreads();

    run_passA(sm);
    __syncthreads();
    run_passB(sm);
    __syncthreads();
    run_passC(sm);
    __syncthreads();
    run_passD(sm);
    __syncthreads();

    float acc[NQ];
    run_passE(sm, acc);

#pragma unroll
    for (int w = 0; w < NQ; ++w)
#pragma unroll
        for (int off = 16; off > 0; off >>= 1)
            acc[w] += __shfl_xor_sync(0xffffffffu, acc[w], off);

    const int warp = tid >> 5, lane = tid & 31;
    if (lane == 0) {
#pragma unroll
        for (int w = 0; w < NQ; ++w) sm->red[warp * NQ + w] = acc[w];
    }
    __syncthreads();
    if (tid < NQ) {
        float s = 0.f;
#pragma unroll
        for (int ww = 0; ww < NT / 32; ++ww) s += sm->red[ww * NQ + tid];
        out[b * NQ + tid] = s;
    }
}

} // namespace

extern "C" void kernel_launch(void* const* d_in, const int* in_sizes, int n_in,
                              void* d_out, int out_size) {
    const float* cp = (const float*)d_in[0];
    const float* p  = (const float*)d_in[1];
    float* out = (float*)d_out;
    const int B = in_sizes[0] / NQ;   // 512
    cudaFuncSetAttribute(qsim_kernel, cudaFuncAttributeMaxDynamicSharedMemorySize,
                         (int)sizeof(Smem));
    qsim_kernel<<<B, NT, sizeof(Smem)>>>(cp, p, out);
}

// round 12
// speedup vs baseline: 1.2638x; 1.1480x over previous
#include <cuda_runtime.h>
#include <stdint.h>

namespace {
typedef unsigned long long u64;

constexpr int NQ = 14;
constexpr int NS = 1 << NQ;          // 16384 amplitudes
constexpr int NT = 512;              // threads per CTA

struct Smem {
    float2 st[NS];                    // state, XOR-swizzled; (i,i^1) share a 16B block
    float  pbuf[NS];                  // permuted probabilities (bank-swizzled layout)
    float2 T[7][4];                   // pair tables: prefix circuit per bit-pair
    float pc[21], ps[21];             // slots 0-6 XX2 (cp col 7+s), 7-20 RX3 (qubit s-7)
    float red[(NT / 32) * NQ];
};

// Compile-time inverse of the composed MCX permutation, pre-composed with the
// pbuf bank swizzle phys = i ^ (((i>>5)&7)<<2) (kills pass-E LDS conflicts).
struct InvTab { uint16_t v[NS]; };
__host__ __device__ constexpr InvTab make_inv() {
    InvTab t{};
    for (int i = 0; i < NS; ++i) {
        int j = i;
        for (int w = NQ - 1; w >= 0; --w) {
            const int c1 = NQ - 1 - w;
            const int c2 = NQ - 1 - ((w + 1) % NQ);
            const int tt = NQ - 1 - ((w + 2) % NQ);
            const int b1 = (j >> c1) & 1;
            const int b2 = (j >> c2) & 1;
            if (b1 & (b2 ^ 1)) j ^= (1 << tt);
        }
        t.v[j] = (uint16_t)(i ^ (((i >> 5) & 7) << 2));   // store swizzled target
    }
    return t;
}
__device__ constexpr InvTab g_inv_tab = make_inv();

// ---- packed f32x2 helpers (FFMA2 path; only reachable via PTX) ----
__device__ __forceinline__ u64 pack2(float lo, float hi) {
    u64 r; asm("mov.b64 %0, {%1, %2};" : "=l"(r) : "f"(lo), "f"(hi)); return r;
}
__device__ __forceinline__ void unpack2(u64 v, float& lo, float& hi) {
    asm("mov.b64 {%0, %1}, %2;" : "=f"(lo), "=f"(hi) : "l"(v));
}
__device__ __forceinline__ u64 bcast2(float x) { return pack2(x, x); }
__device__ __forceinline__ u64 swap2(u64 v) {
    float a, b; unpack2(v, a, b); return pack2(b, a);
}
__device__ __forceinline__ u64 fma2(u64 a, u64 b, u64 c) {
    u64 d; asm("fma.rn.f32x2 %0, %1, %2, %3;" : "=l"(d) : "l"(a), "l"(b), "l"(c)); return d;
}
__device__ __forceinline__ u64 mul2(u64 a, u64 b) {
    u64 d; asm("mul.rn.f32x2 %0, %1, %2;" : "=l"(d) : "l"(a), "l"(b)); return d;
}

__device__ __forceinline__ float2 cmul(float2 a, float2 b) {
    return make_float2(fmaf(a.x, b.x, -a.y * b.y), fmaf(a.x, b.y, a.y * b.x));
}

// XOR-linear swizzle; index bit0 -> addr bit3 ONLY, so (i, i^1) is one aligned 16B block.
__device__ __host__ __forceinline__ uint32_t swaddr(uint32_t i) {
    return (i << 3) ^ ((i >> 1) & 0x70u);
}
__device__ __forceinline__ float4 ld4(const Smem* sm, uint32_t off) {
    return *reinterpret_cast<const float4*>(reinterpret_cast<const char*>(sm->st) + off);
}
__device__ __forceinline__ void st4(Smem* sm, uint32_t off, float4 v) {
    *reinterpret_cast<float4*>(reinterpret_cast<char*>(sm->st) + off) = v;
}
// load/store a packed bit0-pair: block = [re0 im0 re1 im1]
__device__ __forceinline__ void ld2(const Smem* sm, uint32_t off, u64& R, u64& I) {
    const float4 v = ld4(sm, off);
    R = pack2(v.x, v.z); I = pack2(v.y, v.w);
}
__device__ __forceinline__ void st2(Smem* sm, uint32_t off, u64 R, u64 I) {
    float r0, r1, i0, i1; unpack2(R, r0, r1); unpack2(I, i0, i1);
    st4(sm, off, make_float4(r0, i0, r1, i1));
}

// Lane-uniform packed butterfly gates (gate dims exclude bit0).
template<int G, int NG>
__device__ __forceinline__ void apply_gates2(u64 (&Re)[1 << G], u64 (&Im)[1 << G],
                                             const int (&combos)[NG],
                                             const float (&cg)[NG], const float (&sg)[NG]) {
#pragma unroll
    for (int g = 0; g < NG; ++g) {
        const int cb = combos[g], lb = cb & (-cb);
        const u64 cP = bcast2(cg[g]), sP = bcast2(sg[g]), nsP = bcast2(-sg[g]);
#pragma unroll
        for (int t = 0; t < (1 << G); ++t) {
            if ((t & lb) == 0) {
                const int u = t ^ cb;
                const u64 r0 = fma2(cP, Re[t], mul2(sP,  Im[u]));
                const u64 i0 = fma2(cP, Im[t], mul2(nsP, Re[u]));
                const u64 r1 = fma2(cP, Re[u], mul2(sP,  Im[t]));
                const u64 i1 = fma2(cP, Im[u], mul2(nsP, Re[t]));
                Re[t] = r0; Im[t] = i0; Re[u] = r1; Im[u] = i1;
            }
        }
    }
}

// Pass A: generate packed state from pair tables + XX(9,10),(11,12) + RX q9-12.
__device__ __forceinline__ void run_passA(Smem* sm) {
    constexpr int combos[6] = {1, 4, 2, 3, 8, 12};
    constexpr int slots[6]  = {4, 5, 16, 17, 18, 19};
    float cg[6], sg[6];
#pragma unroll
    for (int g = 0; g < 6; ++g) { cg[g] = sm->pc[slots[g]]; sg[g] = sm->ps[slots[g]]; }

    const int tid = threadIdx.x;                // exactly 512 orbit-pairs
    const int rep = tid << 5;                   // bits 5-13 = tid bits 0-8; bit0 = 0
    const uint32_t abase = swaddr((uint32_t)rep);
    const float2 base = cmul(cmul(sm->T[3][(rep >> 6) & 3], sm->T[4][(rep >> 8) & 3]),
                             cmul(sm->T[5][(rep >> 10) & 3], sm->T[6][(rep >> 12) & 3]));
    const int b5 = tid & 1;
    const float2 q2x[2] = { cmul(base, sm->T[2][2 * b5]),
                            cmul(base, sm->T[2][1 + 2 * b5]) };      // index = bit4
    float2 m8[2][4];
#pragma unroll
    for (int b4 = 0; b4 < 2; ++b4)
#pragma unroll
        for (int j23 = 0; j23 < 4; ++j23)
            m8[b4][j23] = cmul(q2x[b4], sm->T[1][j23]);
    // packed T0 lanes: lane0 = bit0=0 entry, lane1 = bit0=1 entry
    u64 T0re[2], T0im[2];
#pragma unroll
    for (int b1 = 0; b1 < 2; ++b1) {
        T0re[b1] = pack2(sm->T[0][2 * b1].x, sm->T[0][2 * b1 + 1].x);
        T0im[b1] = pack2(sm->T[0][2 * b1].y, sm->T[0][2 * b1 + 1].y);
    }
    u64 Re[16], Im[16];
#pragma unroll
    for (int t = 0; t < 16; ++t) {
        const int t0 = t & 1, t1 = (t >> 1) & 1, t2 = (t >> 2) & 1, t3 = (t >> 3) & 1;
        const float2 m = m8[t0 ^ t1][(t0 << 1) | (t2 ^ t3)];
        const u64 mx = bcast2(m.x), my = bcast2(m.y), nmy = bcast2(-m.y);
        Re[t] = fma2(mx, T0re[t2], mul2(nmy, T0im[t2]));
        Im[t] = fma2(mx, T0im[t2], mul2(my,  T0re[t2]));
    }
    apply_gates2<4, 6>(Re, Im, combos, cg, sg);
#pragma unroll
    for (int t = 0; t < 16; ++t) {
        uint32_t x = 0;
        if (t & 1) x ^= 0x18u;
        if (t & 2) x ^= 0x10u;
        if (t & 4) x ^= 0x06u;
        if (t & 8) x ^= 0x04u;
        st2(sm, abase ^ swaddr(x), Re[t], Im[t]);
    }
}

// Pass B: XX(13,0), RX q0, RX q13 (bit0-involved -> lane swaps), XX(7,8), RX q7, RX q8.
__device__ __forceinline__ void run_passB(Smem* sm) {
    const float c1 = sm->pc[6],  s1 = sm->ps[6];    // XX(13,0)
    const float c2 = sm->pc[7],  s2 = sm->ps[7];    // RX q0  (bit13)
    const float c3 = sm->pc[20], s3 = sm->ps[20];   // RX q13 (bit0)
    constexpr int combosU[3] = {2, 4, 6};           // XX(7,8), RX q7, RX q8
    constexpr int slotsU[3]  = {3, 14, 15};
    float cgU[3], sgU[3];
#pragma unroll
    for (int g = 0; g < 3; ++g) { cgU[g] = sm->pc[slotsU[g]]; sgU[g] = sm->ps[slotsU[g]]; }
#pragma unroll
    for (int it = 0; it < 2; ++it) {
        const int k = threadIdx.x + it * NT;
        const int rep = ((k & 0xF) << 1) | ((k >> 4) << 7);   // bit0 = 0
        const uint32_t abase = swaddr((uint32_t)rep);
        u64 Re[8], Im[8];                            // dims: t0=0x2000, t1=0x60, t2=0x40
#pragma unroll
        for (int t = 0; t < 8; ++t) {
            uint32_t x = 0;
            if (t & 1) x ^= 0x2000u;
            if (t & 2) x ^= 0x60u;
            if (t & 4) x ^= 0x40u;
            ld2(sm, abase ^ swaddr(x), Re[t], Im[t]);
        }
        {   // XX(13,0): pairs (t, t^1[dim 0x2000]) with cross-lane partner
            const u64 cP = bcast2(c1), sP = bcast2(s1), nsP = bcast2(-s1);
#pragma unroll
            for (int t = 0; t < 8; t += 2) {
                const int u = t + 1;
                const u64 sIu = swap2(Im[u]), sRu = swap2(Re[u]);
                const u64 sIt = swap2(Im[t]), sRt = swap2(Re[t]);
                const u64 r0 = fma2(cP, Re[t], mul2(sP,  sIu));
                const u64 i0 = fma2(cP, Im[t], mul2(nsP, sRu));
                const u64 r1 = fma2(cP, Re[u], mul2(sP,  sIt));
                const u64 i1 = fma2(cP, Im[u], mul2(nsP, sRt));
                Re[t] = r0; Im[t] = i0; Re[u] = r1; Im[u] = i1;
            }
        }
        {   // RX q0 (bit13): lane-uniform pairs (t, t^1)
            const u64 cP = bcast2(c2), sP = bcast2(s2), nsP = bcast2(-s2);
#pragma unroll
            for (int t = 0; t < 8; t += 2) {
                const int u = t + 1;
                const u64 r0 = fma2(cP, Re[t], mul2(sP,  Im[u]));
                const u64 i0 = fma2(cP, Im[t], mul2(nsP, Re[u]));
                const u64 r1 = fma2(cP, Re[u], mul2(sP,  Im[t]));
                const u64 i1 = fma2(cP, Im[u], mul2(nsP, Re[t]));
                Re[t] = r0; Im[t] = i0; Re[u] = r1; Im[u] = i1;
            }
        }
        {   // RX q13 (bit0): within-element lane butterfly
            const u64 cP = bcast2(c3), sP = bcast2(s3), nsP = bcast2(-s3);
#pragma unroll
            for (int t = 0; t < 8; ++t) {
                const u64 sI = swap2(Im[t]), sR = swap2(Re[t]);
                const u64 r = fma2(cP, Re[t], mul2(sP,  sI));
                const u64 i = fma2(cP, Im[t], mul2(nsP, sR));
                Re[t] = r; Im[t] = i;
            }
        }
        apply_gates2<3, 3>(Re, Im, combosU, cgU, sgU);
#pragma unroll
        for (int t = 0; t < 8; ++t) {
            uint32_t x = 0;
            if (t & 1) x ^= 0x2000u;
            if (t & 2) x ^= 0x60u;
            if (t & 4) x ^= 0x40u;
            st2(sm, abase ^ swaddr(x), Re[t], Im[t]);
        }
    }
}

// Pass C: XX(1,2), RX q1,q2, XX(3,4), RX q3,q4 — fully lane-uniform.
__device__ __forceinline__ void run_passC(Smem* sm) {
    constexpr int combos[6] = {1, 2, 3, 4, 8, 12};
    constexpr int slots[6]  = {0, 8, 9, 1, 10, 11};
    float cg[6], sg[6];
#pragma unroll
    for (int g = 0; g < 6; ++g) { cg[g] = sm->pc[slots[g]]; sg[g] = sm->ps[slots[g]]; }
    const int tid = threadIdx.x;                   // 512 orbit-pairs
    const int rep = ((tid << 1) & 0x1FF) | ((tid >> 8) << 13);   // bit0 = 0
    const uint32_t abase = swaddr((uint32_t)rep);
    u64 Re[16], Im[16];
#pragma unroll
    for (int t = 0; t < 16; ++t) {
        uint32_t x = 0;
        if (t & 1) x ^= 0x1800u;
        if (t & 2) x ^= 0x1000u;
        if (t & 4) x ^= 0x600u;
        if (t & 8) x ^= 0x400u;
        ld2(sm, abase ^ swaddr(x), Re[t], Im[t]);
    }
    apply_gates2<4, 6>(Re, Im, combos, cg, sg);
#pragma unroll
    for (int t = 0; t < 16; ++t) {
        uint32_t x = 0;
        if (t & 1) x ^= 0x1800u;
        if (t & 2) x ^= 0x1000u;
        if (t & 4) x ^= 0x600u;
        if (t & 8) x ^= 0x400u;
        st2(sm, abase ^ swaddr(x), Re[t], Im[t]);
    }
}

// Pass D: XX(5,6) + RX q5,q6 (lane-uniform) + packed |amp|^2 + permuted scatter.
__device__ __forceinline__ void run_passD(Smem* sm) {
    constexpr int combos[3] = {1, 2, 3};
    constexpr int slots[3]  = {2, 12, 13};
    constexpr int XT[4] = {0, 0x180, 0x100, 0x080};
    float cg[3], sg[3];
#pragma unroll
    for (int g = 0; g < 3; ++g) { cg[g] = sm->pc[slots[g]]; sg[g] = sm->ps[slots[g]]; }
#pragma unroll
    for (int it = 0; it < 4; ++it) {
        const int kp = threadIdx.x + it * NT;
        const int rep = ((kp << 1) & 0x7F) | ((kp >> 6) << 9);   // bit0 = 0
        const uint32_t abase = swaddr((uint32_t)rep);
        u64 Re[4], Im[4];
#pragma unroll
        for (int t = 0; t < 4; ++t) ld2(sm, abase ^ swaddr((uint32_t)XT[t]), Re[t], Im[t]);
        apply_gates2<2, 3>(Re, Im, combos, cg, sg);
#pragma unroll
        for (int t = 0; t < 4; ++t) {
            const u64 prP = fma2(Re[t], Re[t], mul2(Im[t], Im[t]));
            float p0, p1; unpack2(prP, p0, p1);
            sm->pbuf[(int)g_inv_tab.v[rep ^ XT[t]]]     = p0;   // table is pre-swizzled
            sm->pbuf[(int)g_inv_tab.v[rep ^ XT[t] ^ 1]] = p1;
        }
    }
}

// Pass E: Walsh-style sign-tree reduction; de-swizzled conflict-free loads.
__device__ __forceinline__ void run_passE(Smem* sm, float (&acc)[NQ]) {
    const int tid = threadIdx.x;
    const int c2 = tid & 7;                       // pbuf bank-swizzle constant
    float pv[32];
#pragma unroll
    for (int q = 0; q < 8; ++q) {
        // logical chunk q lives at physical chunk q^c2 within this thread's block
        const float4 v = reinterpret_cast<const float4*>(sm->pbuf)[tid * 8 + (q ^ c2)];
        pv[4 * q + 0] = v.x; pv[4 * q + 1] = v.y; pv[4 * q + 2] = v.z; pv[4 * q + 3] = v.w;
    }
    float D0 = 0.f, D1 = 0.f, D2 = 0.f, D3 = 0.f;
    float s16[16];
#pragma unroll
    for (int i = 0; i < 16; ++i) { s16[i] = pv[2*i] + pv[2*i+1]; D0 += pv[2*i] - pv[2*i+1]; }
    float s8[8];
#pragma unroll
    for (int i = 0; i < 8; ++i)  { s8[i] = s16[2*i] + s16[2*i+1]; D1 += s16[2*i] - s16[2*i+1]; }
    float s4[4];
#pragma unroll
    for (int i = 0; i < 4; ++i)  { s4[i] = s8[2*i] + s8[2*i+1]; D2 += s8[2*i] - s8[2*i+1]; }
    float s2a[2];
#pragma unroll
    for (int i = 0; i < 2; ++i)  { s2a[i] = s4[2*i] + s4[2*i+1]; D3 += s4[2*i] - s4[2*i+1]; }
    const float S  = s2a[0] + s2a[1];
    const float D4 = s2a[0] - s2a[1];
    acc[13] = D0; acc[12] = D1; acc[11] = D2; acc[10] = D3; acc[9] = D4;
#pragma unroll
    for (int bb = 5; bb <= 13; ++bb)
        acc[13 - bb] = ((tid >> (bb - 5)) & 1) ? -S : S;
}

__global__ __launch_bounds__(NT, 1)
void qsim_kernel(const float* __restrict__ cp, const float* __restrict__ p,
                 float* __restrict__ out) {
    extern __shared__ char smraw[];
    Smem* sm = reinterpret_cast<Smem*>(smraw);
    const int tid = threadIdx.x;
    const int b = blockIdx.x;

    if (tid < NQ) {
        const int w = tid;
        float sn, cs;
        if (w >= 7) {
            sincosf(0.5f * cp[b * NQ + w], &sn, &cs);
            sm->pc[w - 7] = cs; sm->ps[w - 7] = sn;
        }
        sincosf(0.5f * p[(b * 3 + 2) * NQ + w], &sn, &cs);
        sm->pc[7 + w] = cs; sm->ps[7 + w] = sn;
    }
    // Pair tables: T_m for bit-pair (2m+1, 2m) = qubit pair (2k, 2k+1), k = 6-m.
    if (tid < 7) {
        const int m = tid, k = 6 - m;
        const int qa = 2 * k, qb = 2 * k + 1;
        float sa, ca, sb, cb, sx, cx;
        sincosf(0.5f * p[(b * 3 + 0) * NQ + qa], &sa, &ca);
        sincosf(0.5f * p[(b * 3 + 0) * NQ + qb], &sb, &cb);
        sincosf(0.5f * cp[b * NQ + k], &sx, &cx);
        float2 v[4] = { make_float2(ca * cb, 0.f), make_float2(0.f, -ca * sb),
                        make_float2(0.f, -sa * cb), make_float2(-sa * sb, 0.f) };
        float2 u[4];
#pragma unroll
        for (int j = 0; j < 4; ++j) {
            const float2 pv = v[j], qv = v[j ^ 3];
            u[j] = make_float2(fmaf(cx, pv.x,  sx * qv.y), fmaf(cx, pv.y, -sx * qv.x));
        }
        const float tza = p[(b * 3 + 1) * NQ + qa];
        const float tzb = p[(b * 3 + 1) * NQ + qb];
#pragma unroll
        for (int j = 0; j < 4; ++j) {
            const float ang = 0.5f * (((j & 2) ? tza : -tza) + ((j & 1) ? tzb : -tzb));
            float se, ce;
            sincosf(ang, &se, &ce);
            sm->T[m][j] = cmul(u[j], make_float2(ce, se));
        }
    }
    __syncthreads();

    run_passA(sm);
    __syncthreads();
    run_passB(sm);
    __syncthreads();
    run_passC(sm);
    __syncthreads();
    run_passD(sm);
    __syncthreads();

    float acc[NQ];
    run_passE(sm, acc);

#pragma unroll
    for (int w = 0; w < NQ; ++w)
#pragma unroll
        for (int off = 16; off > 0; off >>= 1)
            acc[w] += __shfl_xor_sync(0xffffffffu, acc[w], off);

    const int warp = tid >> 5, lane = tid & 31;
    if (lane == 0) {
#pragma unroll
        for (int w = 0; w < NQ; ++w) sm->red[warp * NQ + w] = acc[w];
    }
    __syncthreads();
    if (tid < NQ) {
        float s = 0.f;
#pragma unroll
        for (int ww = 0; ww < NT / 32; ++ww) s += sm->red[ww * NQ + tid];
        out[b * NQ + tid] = s;
    }
}

} // namespace

extern "C" void kernel_launch(void* const* d_in, const int* in_sizes, int n_in,
                              void* d_out, int out_size) {
    const float* cp = (const float*)d_in[0];
    const float* p  = (const float*)d_in[1];
    float* out = (float*)d_out;
    const int B = in_sizes[0] / NQ;   // 512
    cudaFuncSetAttribute(qsim_kernel, cudaFuncAttributeMaxDynamicSharedMemorySize,
                         (int)sizeof(Smem));
    qsim_kernel<<<B, NT, sizeof(Smem)>>>(cp, p, out);
}

// round 14
// speedup vs baseline: 1.3100x; 1.0366x over previous
#include <cuda_runtime.h>
#include <stdint.h>

namespace {
typedef unsigned long long u64;

constexpr int NQ = 14;
constexpr int NS = 1 << NQ;          // 16384 amplitudes
constexpr int NT = 512;              // threads per CTA

struct Smem {
    float2 st[NS];                    // state; block layout [r0 r1 i0 i1] per (i,i^1) pair
    float  pbuf[NS];                  // permuted probabilities (bank-swizzled layout)
    float2 T[7][4];                   // pair tables: prefix circuit per bit-pair
    float pc[21], ps[21];             // slots 0-6 XX2 (cp col 7+s), 7-20 RX3 (qubit s-7)
    float red[(NT / 32) * NQ];
};

// Compile-time inverse of the composed MCX permutation, pre-composed with the
// pbuf bank swizzle phys = i ^ (((i>>5)&7)<<2) (kills pass-E LDS conflicts).
struct InvTab { uint16_t v[NS]; };
__host__ __device__ constexpr InvTab make_inv() {
    InvTab t{};
    for (int i = 0; i < NS; ++i) {
        int j = i;
        for (int w = NQ - 1; w >= 0; --w) {
            const int c1 = NQ - 1 - w;
            const int c2 = NQ - 1 - ((w + 1) % NQ);
            const int tt = NQ - 1 - ((w + 2) % NQ);
            const int b1 = (j >> c1) & 1;
            const int b2 = (j >> c2) & 1;
            if (b1 & (b2 ^ 1)) j ^= (1 << tt);
        }
        t.v[j] = (uint16_t)(i ^ (((i >> 5) & 7) << 2));   // store swizzled target
    }
    return t;
}
__device__ constexpr InvTab g_inv_tab = make_inv();

// ---- packed f32x2 helpers (FFMA2 path; only reachable via PTX) ----
__device__ __forceinline__ u64 pack2(float lo, float hi) {
    u64 r; asm("mov.b64 %0, {%1, %2};" : "=l"(r) : "f"(lo), "f"(hi)); return r;
}
__device__ __forceinline__ void unpack2(u64 v, float& lo, float& hi) {
    asm("mov.b64 {%0, %1}, %2;" : "=f"(lo), "=f"(hi) : "l"(v));
}
__device__ __forceinline__ u64 bcast2(float x) { return pack2(x, x); }
__device__ __forceinline__ u64 swap2(u64 v) {
    float a, b; unpack2(v, a, b); return pack2(b, a);
}
__device__ __forceinline__ u64 fma2(u64 a, u64 b, u64 c) {
    u64 d; asm("fma.rn.f32x2 %0, %1, %2, %3;" : "=l"(d) : "l"(a), "l"(b), "l"(c)); return d;
}
__device__ __forceinline__ u64 mul2(u64 a, u64 b) {
    u64 d; asm("mul.rn.f32x2 %0, %1, %2;" : "=l"(d) : "l"(a), "l"(b)); return d;
}

__device__ __forceinline__ float2 cmul(float2 a, float2 b) {
    return make_float2(fmaf(a.x, b.x, -a.y * b.y), fmaf(a.x, b.y, a.y * b.x));
}

// shared-state-space address of a pointer
__device__ __forceinline__ uint32_t smem_u32(const void* p) {
    uint32_t r;
    asm("{ .reg .u64 t; cvta.to.shared.u64 t, %1; cvt.u32.u64 %0, t; }" : "=r"(r) : "l"(p));
    return r;
}

// XOR-linear swizzle; index bit0 -> addr bit3 ONLY, so (i, i^1) is one aligned 16B block.
__device__ __host__ __forceinline__ uint32_t swaddr(uint32_t i) {
    return (i << 3) ^ ((i >> 1) & 0x70u);
}

// Zero-mov packed pair access: block = [r0 r1 i0 i1] -> R = (r0,r1), I = (i0,i1)
__device__ __forceinline__ void ld2(uint32_t addr, u64& R, u64& I) {
    asm volatile("ld.shared.v2.b64 {%0, %1}, [%2];" : "=l"(R), "=l"(I) : "r"(addr));
}
__device__ __forceinline__ void st2(uint32_t addr, u64 R, u64 I) {
    asm volatile("st.shared.v2.b64 [%0], {%1, %2};" :: "r"(addr), "l"(R), "l"(I) : "memory");
}

// Lane-uniform packed butterfly gates (gate dims exclude bit0).
template<int G, int NG>
__device__ __forceinline__ void apply_gates2(u64 (&Re)[1 << G], u64 (&Im)[1 << G],
                                             const int (&combos)[NG],
                                             const float (&cg)[NG], const float (&sg)[NG]) {
#pragma unroll
    for (int g = 0; g < NG; ++g) {
        const int cb = combos[g], lb = cb & (-cb);
        const u64 cP = bcast2(cg[g]), sP = bcast2(sg[g]), nsP = bcast2(-sg[g]);
#pragma unroll
        for (int t = 0; t < (1 << G); ++t) {
            if ((t & lb) == 0) {
                const int u = t ^ cb;
                const u64 r0 = fma2(cP, Re[t], mul2(sP,  Im[u]));
                const u64 i0 = fma2(cP, Im[t], mul2(nsP, Re[u]));
                const u64 r1 = fma2(cP, Re[u], mul2(sP,  Im[t]));
                const u64 i1 = fma2(cP, Im[u], mul2(nsP, Re[t]));
                Re[t] = r0; Im[t] = i0; Re[u] = r1; Im[u] = i1;
            }
        }
    }
}

// Pass A: generate packed state from pair tables + XX(9,10),(11,12) + RX q9-12.
__device__ __forceinline__ void run_passA(Smem* sm, uint32_t sbase) {
    constexpr int combos[6] = {1, 4, 2, 3, 8, 12};
    constexpr int slots[6]  = {4, 5, 16, 17, 18, 19};
    float cg[6], sg[6];
#pragma unroll
    for (int g = 0; g < 6; ++g) { cg[g] = sm->pc[slots[g]]; sg[g] = sm->ps[slots[g]]; }

    const int tid = threadIdx.x;                // exactly 512 orbit-pairs
    const int rep = tid << 5;                   // bits 5-13 = tid bits 0-8; bit0 = 0
    const uint32_t obase = swaddr((uint32_t)rep);   // XOR-space orbit base (no sbase!)
    const float2 base = cmul(cmul(sm->T[3][(rep >> 6) & 3], sm->T[4][(rep >> 8) & 3]),
                             cmul(sm->T[5][(rep >> 10) & 3], sm->T[6][(rep >> 12) & 3]));
    const int b5 = tid & 1;
    const float2 q2x[2] = { cmul(base, sm->T[2][2 * b5]),
                            cmul(base, sm->T[2][1 + 2 * b5]) };      // index = bit4
    float2 m8[2][4];
#pragma unroll
    for (int b4 = 0; b4 < 2; ++b4)
#pragma unroll
        for (int j23 = 0; j23 < 4; ++j23)
            m8[b4][j23] = cmul(q2x[b4], sm->T[1][j23]);
    // packed T0 lanes: lane0 = bit0=0 entry, lane1 = bit0=1 entry
    u64 T0re[2], T0im[2];
#pragma unroll
    for (int b1 = 0; b1 < 2; ++b1) {
        T0re[b1] = pack2(sm->T[0][2 * b1].x, sm->T[0][2 * b1 + 1].x);
        T0im[b1] = pack2(sm->T[0][2 * b1].y, sm->T[0][2 * b1 + 1].y);
    }
    u64 Re[16], Im[16];
#pragma unroll
    for (int t = 0; t < 16; ++t) {
        const int t0 = t & 1, t1 = (t >> 1) & 1, t2 = (t >> 2) & 1, t3 = (t >> 3) & 1;
        const float2 m = m8[t0 ^ t1][(t0 << 1) | (t2 ^ t3)];
        const u64 mx = bcast2(m.x), my = bcast2(m.y), nmy = bcast2(-m.y);
        Re[t] = fma2(mx, T0re[t2], mul2(nmy, T0im[t2]));
        Im[t] = fma2(mx, T0im[t2], mul2(my,  T0re[t2]));
    }
    apply_gates2<4, 6>(Re, Im, combos, cg, sg);
#pragma unroll
    for (int t = 0; t < 16; ++t) {
        uint32_t x = 0;
        if (t & 1) x ^= 0x18u;
        if (t & 2) x ^= 0x10u;
        if (t & 4) x ^= 0x06u;
        if (t & 8) x ^= 0x04u;
        st2(sbase + (obase ^ swaddr(x)), Re[t], Im[t]);
    }
}

// Pass B: XX(13,0), RX q0, RX q13 (bit0-involved -> lane swaps), XX(7,8), RX q7, RX q8.
__device__ __forceinline__ void run_passB(Smem* sm, uint32_t sbase) {
    const float c1 = sm->pc[6],  s1 = sm->ps[6];    // XX(13,0)
    const float c2 = sm->pc[7],  s2 = sm->ps[7];    // RX q0  (bit13)
    const float c3 = sm->pc[20], s3 = sm->ps[20];   // RX q13 (bit0)
    constexpr int combosU[3] = {2, 4, 6};           // XX(7,8), RX q7, RX q8
    constexpr int slotsU[3]  = {3, 14, 15};
    float cgU[3], sgU[3];
#pragma unroll
    for (int g = 0; g < 3; ++g) { cgU[g] = sm->pc[slotsU[g]]; sgU[g] = sm->ps[slotsU[g]]; }
#pragma unroll
    for (int it = 0; it < 2; ++it) {
        const int k = threadIdx.x + it * NT;
        const int rep = ((k & 0xF) << 1) | ((k >> 4) << 7);   // bit0 = 0
        const uint32_t obase = swaddr((uint32_t)rep);
        u64 Re[8], Im[8];                            // dims: t0=0x2000, t1=0x60, t2=0x40
#pragma unroll
        for (int t = 0; t < 8; ++t) {
            uint32_t x = 0;
            if (t & 1) x ^= 0x2000u;
            if (t & 2) x ^= 0x60u;
            if (t & 4) x ^= 0x40u;
            ld2(sbase + (obase ^ swaddr(x)), Re[t], Im[t]);
        }
        {   // XX(13,0): pairs (t, t^1[dim 0x2000]) with cross-lane partner
            const u64 cP = bcast2(c1), sP = bcast2(s1), nsP = bcast2(-s1);
#pragma unroll
            for (int t = 0; t < 8; t += 2) {
                const int u = t + 1;
                const u64 sIu = swap2(Im[u]), sRu = swap2(Re[u]);
                const u64 sIt = swap2(Im[t]), sRt = swap2(Re[t]);
                const u64 r0 = fma2(cP, Re[t], mul2(sP,  sIu));
                const u64 i0 = fma2(cP, Im[t], mul2(nsP, sRu));
                const u64 r1 = fma2(cP, Re[u], mul2(sP,  sIt));
                const u64 i1 = fma2(cP, Im[u], mul2(nsP, sRt));
                Re[t] = r0; Im[t] = i0; Re[u] = r1; Im[u] = i1;
            }
        }
        {   // RX q0 (bit13): lane-uniform pairs (t, t^1)
            const u64 cP = bcast2(c2), sP = bcast2(s2), nsP = bcast2(-s2);
#pragma unroll
            for (int t = 0; t < 8; t += 2) {
                const int u = t + 1;
                const u64 r0 = fma2(cP, Re[t], mul2(sP,  Im[u]));
                const u64 i0 = fma2(cP, Im[t], mul2(nsP, Re[u]));
                const u64 r1 = fma2(cP, Re[u], mul2(sP,  Im[t]));
                const u64 i1 = fma2(cP, Im[u], mul2(nsP, Re[t]));
                Re[t] = r0; Im[t] = i0; Re[u] = r1; Im[u] = i1;
            }
        }
        {   // RX q13 (bit0): within-element lane butterfly
            const u64 cP = bcast2(c3), sP = bcast2(s3), nsP = bcast2(-s3);
#pragma unroll
            for (int t = 0; t < 8; ++t) {
                const u64 sI = swap2(Im[t]), sR = swap2(Re[t]);
                const u64 r = fma2(cP, Re[t], mul2(sP,  sI));
                const u64 i = fma2(cP, Im[t], mul2(nsP, sR));
                Re[t] = r; Im[t] = i;
            }
        }
        apply_gates2<3, 3>(Re, Im, combosU, cgU, sgU);
#pragma unroll
        for (int t = 0; t < 8; ++t) {
            uint32_t x = 0;
            if (t & 1) x ^= 0x2000u;
            if (t & 2) x ^= 0x60u;
            if (t & 4) x ^= 0x40u;
            st2(sbase + (obase ^ swaddr(x)), Re[t], Im[t]);
        }
    }
}

// Pass C: XX(1,2), RX q1,q2, XX(3,4), RX q3,q4 — fully lane-uniform.
__device__ __forceinline__ void run_passC(Smem* sm, uint32_t sbase) {
    constexpr int combos[6] = {1, 2, 3, 4, 8, 12};
    constexpr int slots[6]  = {0, 8, 9, 1, 10, 11};
    float cg[6], sg[6];
#pragma unroll
    for (int g = 0; g < 6; ++g) { cg[g] = sm->pc[slots[g]]; sg[g] = sm->ps[slots[g]]; }
    const int tid = threadIdx.x;                   // 512 orbit-pairs
    const int rep = ((tid << 1) & 0x1FF) | ((tid >> 8) << 13);   // bit0 = 0
    const uint32_t obase = swaddr((uint32_t)rep);
    u64 Re[16], Im[16];
#pragma unroll
    for (int t = 0; t < 16; ++t) {
        uint32_t x = 0;
        if (t & 1) x ^= 0x1800u;
        if (t & 2) x ^= 0x1000u;
        if (t & 4) x ^= 0x600u;
        if (t & 8) x ^= 0x400u;
        ld2(sbase + (obase ^ swaddr(x)), Re[t], Im[t]);
    }
    apply_gates2<4, 6>(Re, Im, combos, cg, sg);
#pragma unroll
    for (int t = 0; t < 16; ++t) {
        uint32_t x = 0;
        if (t & 1) x ^= 0x1800u;
        if (t & 2) x ^= 0x1000u;
        if (t & 4) x ^= 0x600u;
        if (t & 8) x ^= 0x400u;
        st2(sbase + (obase ^ swaddr(x)), Re[t], Im[t]);
    }
}

// Pass D: XX(5,6) + RX q5,q6 (lane-uniform) + packed |amp|^2 + permuted scatter.
__device__ __forceinline__ void run_passD(Smem* sm, uint32_t sbase) {
    constexpr int combos[3] = {1, 2, 3};
    constexpr int slots[3]  = {2, 12, 13};
    constexpr int XT[4] = {0, 0x180, 0x100, 0x080};
    float cg[3], sg[3];
#pragma unroll
    for (int g = 0; g < 3; ++g) { cg[g] = sm->pc[slots[g]]; sg[g] = sm->ps[slots[g]]; }
#pragma unroll
    for (int it = 0; it < 4; ++it) {
        const int kp = threadIdx.x + it * NT;
        const int rep = ((kp << 1) & 0x7F) | ((kp >> 6) << 9);   // bit0 = 0
        const uint32_t obase = swaddr((uint32_t)rep);
        u64 Re[4], Im[4];
#pragma unroll
        for (int t = 0; t < 4; ++t)
            ld2(sbase + (obase ^ swaddr((uint32_t)XT[t])), Re[t], Im[t]);
        apply_gates2<2, 3>(Re, Im, combos, cg, sg);
#pragma unroll
        for (int t = 0; t < 4; ++t) {
            const u64 prP = fma2(Re[t], Re[t], mul2(Im[t], Im[t]));
            float p0, p1; unpack2(prP, p0, p1);
            sm->pbuf[(int)g_inv_tab.v[rep ^ XT[t]]]     = p0;   // table is pre-swizzled
            sm->pbuf[(int)g_inv_tab.v[rep ^ XT[t] ^ 1]] = p1;
        }
    }
}

// Pass E: Walsh-style sign-tree reduction; de-swizzled conflict-free loads.
__device__ __forceinline__ void run_passE(Smem* sm, float (&acc)[NQ]) {
    const int tid = threadIdx.x;
    const int c2 = tid & 7;                       // pbuf bank-swizzle constant
    float pv[32];
#pragma unroll
    for (int q = 0; q < 8; ++q) {
        // logical chunk q lives at physical chunk q^c2 within this thread's block
        const float4 v = reinterpret_cast<const float4*>(sm->pbuf)[tid * 8 + (q ^ c2)];
        pv[4 * q + 0] = v.x; pv[4 * q + 1] = v.y; pv[4 * q + 2] = v.z; pv[4 * q + 3] = v.w;
    }
    float D0 = 0.f, D1 = 0.f, D2 = 0.f, D3 = 0.f;
    float s16[16];
#pragma unroll
    for (int i = 0; i < 16; ++i) { s16[i] = pv[2*i] + pv[2*i+1]; D0 += pv[2*i] - pv[2*i+1]; }
    float s8[8];
#pragma unroll
    for (int i = 0; i < 8; ++i)  { s8[i] = s16[2*i] + s16[2*i+1]; D1 += s16[2*i] - s16[2*i+1]; }
    float s4[4];
#pragma unroll
    for (int i = 0; i < 4; ++i)  { s4[i] = s8[2*i] + s8[2*i+1]; D2 += s8[2*i] - s8[2*i+1]; }
    float s2a[2];
#pragma unroll
    for (int i = 0; i < 2; ++i)  { s2a[i] = s4[2*i] + s4[2*i+1]; D3 += s4[2*i] - s4[2*i+1]; }
    const float S  = s2a[0] + s2a[1];
    const float D4 = s2a[0] - s2a[1];
    acc[13] = D0; acc[12] = D1; acc[11] = D2; acc[10] = D3; acc[9] = D4;
#pragma unroll
    for (int bb = 5; bb <= 13; ++bb)
        acc[13 - bb] = ((tid >> (bb - 5)) & 1) ? -S : S;
}

__global__ __launch_bounds__(NT, 1)
void qsim_kernel(const float* __restrict__ cp, const float* __restrict__ p,
                 float* __restrict__ out) {
    extern __shared__ char smraw[];
    Smem* sm = reinterpret_cast<Smem*>(smraw);
    const int tid = threadIdx.x;
    const int b = blockIdx.x;
    const uint32_t sbase = smem_u32(sm->st);

    if (tid < NQ) {
        const int w = tid;
        float sn, cs;
        if (w >= 7) {
            sincosf(0.5f * cp[b * NQ + w], &sn, &cs);
            sm->pc[w - 7] = cs; sm->ps[w - 7] = sn;
        }
        sincosf(0.5f * p[(b * 3 + 2) * NQ + w], &sn, &cs);
        sm->pc[7 + w] = cs; sm->ps[7 + w] = sn;
    }
    // Pair tables: T_m for bit-pair (2m+1, 2m) = qubit pair (2k, 2k+1), k = 6-m.
    if (tid < 7) {
        const int m = tid, k = 6 - m;
        const int qa = 2 * k, qb = 2 * k + 1;
        float sa, ca, sb, cb, sx, cx;
        sincosf(0.5f * p[(b * 3 + 0) * NQ + qa], &sa, &ca);
        sincosf(0.5f * p[(b * 3 + 0) * NQ + qb], &sb, &cb);
        sincosf(0.5f * cp[b * NQ + k], &sx, &cx);
        float2 v[4] = { make_float2(ca * cb, 0.f), make_float2(0.f, -ca * sb),
                        make_float2(0.f, -sa * cb), make_float2(-sa * sb, 0.f) };
        float2 u[4];
#pragma unroll
        for (int j = 0; j < 4; ++j) {
            const float2 pv = v[j], qv = v[j ^ 3];
            u[j] = make_float2(fmaf(cx, pv.x,  sx * qv.y), fmaf(cx, pv.y, -sx * qv.x));
        }
        const float tza = p[(b * 3 + 1) * NQ + qa];
        const float tzb = p[(b * 3 + 1) * NQ + qb];
#pragma unroll
        for (int j = 0; j < 4; ++j) {
            const float ang = 0.5f * (((j & 2) ? tza : -tza) + ((j & 1) ? tzb : -tzb));
            float se, ce;
            sincosf(ang, &se, &ce);
            sm->T[m][j] = cmul(u[j], make_float2(ce, se));
        }
    }
    __syncthreads();

    run_passA(sm, sbase);
    __syncthreads();
    run_passB(sm, sbase);
    __syncthreads();
    run_passC(sm, sbase);
    __syncthreads();
    run_passD(sm, sbase);
    __syncthreads();

    float acc[NQ];
    run_passE(sm, acc);

#pragma unroll
    for (int w = 0; w < NQ; ++w)
#pragma unroll
        for (int off = 16; off > 0; off >>= 1)
            acc[w] += __shfl_xor_sync(0xffffffffu, acc[w], off);

    const int warp = tid >> 5, lane = tid & 31;
    if (lane == 0) {
#pragma unroll
        for (int w = 0; w < NQ; ++w) sm->red[warp * NQ + w] = acc[w];
    }
    __syncthreads();
    if (tid < NQ) {
        float s = 0.f;
#pragma unroll
        for (int ww = 0; ww < NT / 32; ++ww) s += sm->red[ww * NQ + tid];
        out[b * NQ + tid] = s;
    }
}

} // namespace

extern "C" void kernel_launch(void* const* d_in, const int* in_sizes, int n_in,
                              void* d_out, int out_size) {
    const float* cp = (const float*)d_in[0];
    const float* p  = (const float*)d_in[1];
    float* out = (float*)d_out;
    const int B = in_sizes[0] / NQ;   // 512
    cudaFuncSetAttribute(qsim_kernel, cudaFuncAttributeMaxDynamicSharedMemorySize,
                         (int)sizeof(Smem));
    qsim_kernel<<<B, NT, sizeof(Smem)>>>(cp, p, out);
}

// round 15
// speedup vs baseline: 1.5085x; 1.1515x over previous
#include <cuda_runtime.h>
#include <stdint.h>

namespace {
typedef unsigned long long u64;

constexpr int NQ = 14;
constexpr int NS = 1 << NQ;          // 16384 amplitudes
constexpr int NT = 512;              // threads per CTA

struct Smem {
    float2 st[NS];                    // state; block layout [r0 r1 i0 i1] per (i,i^1) pair
    float  pbuf[NS];                  // permuted probabilities (bank-swizzled layout)
    float2 T[7][4];                   // pair tables: prefix circuit per bit-pair
    float pc[21], ps[21];             // per gate slot: pc = cos, ps = tan (s/c)
    float red[(NT / 32) * NQ];
};

// Compile-time inverse of the composed MCX permutation, pre-composed with the
// pbuf bank swizzle phys = i ^ (((i>>5)&7)<<2) (kills pass-E LDS conflicts).
struct InvTab { uint16_t v[NS]; };
__host__ __device__ constexpr InvTab make_inv() {
    InvTab t{};
    for (int i = 0; i < NS; ++i) {
        int j = i;
        for (int w = NQ - 1; w >= 0; --w) {
            const int c1 = NQ - 1 - w;
            const int c2 = NQ - 1 - ((w + 1) % NQ);
            const int tt = NQ - 1 - ((w + 2) % NQ);
            const int b1 = (j >> c1) & 1;
            const int b2 = (j >> c2) & 1;
            if (b1 & (b2 ^ 1)) j ^= (1 << tt);
        }
        t.v[j] = (uint16_t)(i ^ (((i >> 5) & 7) << 2));   // store swizzled target
    }
    return t;
}
__device__ constexpr InvTab g_inv_tab = make_inv();

// ---- packed f32x2 helpers ----
__device__ __forceinline__ u64 pack2(float lo, float hi) {
    u64 r; asm("mov.b64 %0, {%1, %2};" : "=l"(r) : "f"(lo), "f"(hi)); return r;
}
__device__ __forceinline__ void unpack2(u64 v, float& lo, float& hi) {
    asm("mov.b64 {%0, %1}, %2;" : "=f"(lo), "=f"(hi) : "l"(v));
}
__device__ __forceinline__ u64 bcast2(float x) { return pack2(x, x); }
__device__ __forceinline__ u64 swap2(u64 v) {
    float a, b; unpack2(v, a, b); return pack2(b, a);
}
__device__ __forceinline__ u64 fma2(u64 a, u64 b, u64 c) {
    u64 d; asm("fma.rn.f32x2 %0, %1, %2, %3;" : "=l"(d) : "l"(a), "l"(b), "l"(c)); return d;
}
__device__ __forceinline__ u64 mul2(u64 a, u64 b) {
    u64 d; asm("mul.rn.f32x2 %0, %1, %2;" : "=l"(d) : "l"(a), "l"(b)); return d;
}

__device__ __forceinline__ float2 cmul(float2 a, float2 b) {
    return make_float2(fmaf(a.x, b.x, -a.y * b.y), fmaf(a.x, b.y, a.y * b.x));
}

// shared-state-space address of a pointer
__device__ __forceinline__ uint32_t smem_u32(const void* p) {
    uint32_t r;
    asm("{ .reg .u64 t; cvta.to.shared.u64 t, %1; cvt.u32.u64 %0, t; }" : "=r"(r) : "l"(p));
    return r;
}

// XOR-linear swizzle; index bit0 -> addr bit3 ONLY, so (i, i^1) is one aligned 16B block.
__device__ __host__ __forceinline__ uint32_t swaddr(uint32_t i) {
    return (i << 3) ^ ((i >> 1) & 0x70u);
}

// Zero-mov packed pair access: block = [r0 r1 i0 i1] -> R = (r0,r1), I = (i0,i1)
__device__ __forceinline__ void ld2(uint32_t addr, u64& R, u64& I) {
    asm volatile("ld.shared.v2.b64 {%0, %1}, [%2];" : "=l"(R), "=l"(I) : "r"(addr));
}
__device__ __forceinline__ void st2(uint32_t addr, u64 R, u64 I) {
    asm volatile("st.shared.v2.b64 [%0], {%1, %2};" :: "r"(addr), "l"(R), "l"(I) : "memory");
}

// Tangent-form lane-uniform butterflies: [c,-is;-is,c] = c*[1,-it;-it,1]; the cos
// product is folded into generation (pass A). One fma2 per element update.
template<int G, int NG>
__device__ __forceinline__ void apply_gates2(u64 (&Re)[1 << G], u64 (&Im)[1 << G],
                                             const int (&combos)[NG], const float (&tg)[NG]) {
#pragma unroll
    for (int g = 0; g < NG; ++g) {
        const int cb = combos[g], lb = cb & (-cb);
        const u64 tP = bcast2(tg[g]), ntP = bcast2(-tg[g]);
#pragma unroll
        for (int t = 0; t < (1 << G); ++t) {
            if ((t & lb) == 0) {
                const int u = t ^ cb;
                const u64 r0 = fma2(tP,  Im[u], Re[t]);
                const u64 i0 = fma2(ntP, Re[u], Im[t]);
                const u64 r1 = fma2(tP,  Im[t], Re[u]);
                const u64 i1 = fma2(ntP, Re[t], Im[u]);
                Re[t] = r0; Im[t] = i0; Re[u] = r1; Im[u] = i1;
            }
        }
    }
}

// Pass A: generate packed state (scaled by P = prod of all 21 suffix-gate cosines)
// + tan-form XX(9,10),(11,12),RX q9-12.
__device__ __forceinline__ void run_passA(Smem* sm, uint32_t sbase) {
    constexpr int combos[6] = {1, 4, 2, 3, 8, 12};
    constexpr int slots[6]  = {4, 5, 16, 17, 18, 19};
    float tg[6];
#pragma unroll
    for (int g = 0; g < 6; ++g) tg[g] = sm->ps[slots[g]];

    // global cosine product (tree; broadcast LDS reads)
    float P = ((sm->pc[0] * sm->pc[1]) * (sm->pc[2] * sm->pc[3])) *
              ((sm->pc[4] * sm->pc[5]) * (sm->pc[6] * sm->pc[7]));
    P *= ((sm->pc[8] * sm->pc[9]) * (sm->pc[10] * sm->pc[11])) *
         ((sm->pc[12] * sm->pc[13]) * (sm->pc[14] * sm->pc[15]));
    P *= ((sm->pc[16] * sm->pc[17]) * (sm->pc[18] * sm->pc[19])) * sm->pc[20];

    const int tid = threadIdx.x;                // exactly 512 orbit-pairs
    const int rep = tid << 5;                   // bits 5-13 = tid bits 0-8; bit0 = 0
    const uint32_t obase = swaddr((uint32_t)rep);
    float2 base = cmul(cmul(sm->T[3][(rep >> 6) & 3], sm->T[4][(rep >> 8) & 3]),
                       cmul(sm->T[5][(rep >> 10) & 3], sm->T[6][(rep >> 12) & 3]));
    base.x *= P; base.y *= P;                   // fold cosine product in once
    const int b5 = tid & 1;
    const float2 q2x[2] = { cmul(base, sm->T[2][2 * b5]),
                            cmul(base, sm->T[2][1 + 2 * b5]) };      // index = bit4
    float2 m8[2][4];
#pragma unroll
    for (int b4 = 0; b4 < 2; ++b4)
#pragma unroll
        for (int j23 = 0; j23 < 4; ++j23)
            m8[b4][j23] = cmul(q2x[b4], sm->T[1][j23]);
    // packed T0 lanes: lane0 = bit0=0 entry, lane1 = bit0=1 entry
    u64 T0re[2], T0im[2];
#pragma unroll
    for (int b1 = 0; b1 < 2; ++b1) {
        T0re[b1] = pack2(sm->T[0][2 * b1].x, sm->T[0][2 * b1 + 1].x);
        T0im[b1] = pack2(sm->T[0][2 * b1].y, sm->T[0][2 * b1 + 1].y);
    }
    u64 Re[16], Im[16];
#pragma unroll
    for (int t = 0; t < 16; ++t) {
        const int t0 = t & 1, t1 = (t >> 1) & 1, t2 = (t >> 2) & 1, t3 = (t >> 3) & 1;
        const float2 m = m8[t0 ^ t1][(t0 << 1) | (t2 ^ t3)];
        const u64 mx = bcast2(m.x), my = bcast2(m.y), nmy = bcast2(-m.y);
        Re[t] = fma2(mx, T0re[t2], mul2(nmy, T0im[t2]));
        Im[t] = fma2(mx, T0im[t2], mul2(my,  T0re[t2]));
    }
    apply_gates2<4, 6>(Re, Im, combos, tg);
#pragma unroll
    for (int t = 0; t < 16; ++t) {
        uint32_t x = 0;
        if (t & 1) x ^= 0x18u;
        if (t & 2) x ^= 0x10u;
        if (t & 4) x ^= 0x06u;
        if (t & 8) x ^= 0x04u;
        st2(sbase + (obase ^ swaddr(x)), Re[t], Im[t]);
    }
}

// Pass B: XX(13,0), RX q0, RX q13 (bit0-involved -> lane swaps), XX(7,8), RX q7, RX q8.
__device__ __forceinline__ void run_passB(Smem* sm, uint32_t sbase) {
    const float t1 = sm->ps[6];                     // XX(13,0)
    const float t2 = sm->ps[7];                     // RX q0  (bit13)
    const float t3 = sm->ps[20];                    // RX q13 (bit0)
    constexpr int combosU[3] = {2, 4, 6};           // XX(7,8), RX q7, RX q8
    constexpr int slotsU[3]  = {3, 14, 15};
    float tgU[3];
#pragma unroll
    for (int g = 0; g < 3; ++g) tgU[g] = sm->ps[slotsU[g]];
#pragma unroll
    for (int it = 0; it < 2; ++it) {
        const int k = threadIdx.x + it * NT;
        const int rep = ((k & 0xF) << 1) | ((k >> 4) << 7);   // bit0 = 0
        const uint32_t obase = swaddr((uint32_t)rep);
        u64 Re[8], Im[8];                            // dims: t0=0x2000, t1=0x60, t2=0x40
#pragma unroll
        for (int t = 0; t < 8; ++t) {
            uint32_t x = 0;
            if (t & 1) x ^= 0x2000u;
            if (t & 2) x ^= 0x60u;
            if (t & 4) x ^= 0x40u;
            ld2(sbase + (obase ^ swaddr(x)), Re[t], Im[t]);
        }
        {   // XX(13,0): pairs (t, t^1[dim 0x2000]) with cross-lane partner
            const u64 tP = bcast2(t1), ntP = bcast2(-t1);
#pragma unroll
            for (int t = 0; t < 8; t += 2) {
                const int u = t + 1;
                const u64 sIu = swap2(Im[u]), sRu = swap2(Re[u]);
                const u64 sIt = swap2(Im[t]), sRt = swap2(Re[t]);
                const u64 r0 = fma2(tP,  sIu, Re[t]);
                const u64 i0 = fma2(ntP, sRu, Im[t]);
                const u64 r1 = fma2(tP,  sIt, Re[u]);
                const u64 i1 = fma2(ntP, sRt, Im[u]);
                Re[t] = r0; Im[t] = i0; Re[u] = r1; Im[u] = i1;
            }
        }
        {   // RX q0 (bit13): lane-uniform pairs (t, t^1)
            const u64 tP = bcast2(t2), ntP = bcast2(-t2);
#pragma unroll
            for (int t = 0; t < 8; t += 2) {
                const int u = t + 1;
                const u64 r0 = fma2(tP,  Im[u], Re[t]);
                const u64 i0 = fma2(ntP, Re[u], Im[t]);
                const u64 r1 = fma2(tP,  Im[t], Re[u]);
                const u64 i1 = fma2(ntP, Re[t], Im[u]);
                Re[t] = r0; Im[t] = i0; Re[u] = r1; Im[u] = i1;
            }
        }
        {   // RX q13 (bit0): within-element lane butterfly
            const u64 tP = bcast2(t3), ntP = bcast2(-t3);
#pragma unroll
            for (int t = 0; t < 8; ++t) {
                const u64 sI = swap2(Im[t]), sR = swap2(Re[t]);
                const u64 r = fma2(tP,  sI, Re[t]);
                const u64 i = fma2(ntP, sR, Im[t]);
                Re[t] = r; Im[t] = i;
            }
        }
        apply_gates2<3, 3>(Re, Im, combosU, tgU);
#pragma unroll
        for (int t = 0; t < 8; ++t) {
            uint32_t x = 0;
            if (t & 1) x ^= 0x2000u;
            if (t & 2) x ^= 0x60u;
            if (t & 4) x ^= 0x40u;
            st2(sbase + (obase ^ swaddr(x)), Re[t], Im[t]);
        }
    }
}

// Pass C: XX(1,2), RX q1,q2, XX(3,4), RX q3,q4 — fully lane-uniform.
__device__ __forceinline__ void run_passC(Smem* sm, uint32_t sbase) {
    constexpr int combos[6] = {1, 2, 3, 4, 8, 12};
    constexpr int slots[6]  = {0, 8, 9, 1, 10, 11};
    float tg[6];
#pragma unroll
    for (int g = 0; g < 6; ++g) tg[g] = sm->ps[slots[g]];
    const int tid = threadIdx.x;                   // 512 orbit-pairs
    const int rep = ((tid << 1) & 0x1FF) | ((tid >> 8) << 13);   // bit0 = 0
    const uint32_t obase = swaddr((uint32_t)rep);
    u64 Re[16], Im[16];
#pragma unroll
    for (int t = 0; t < 16; ++t) {
        uint32_t x = 0;
        if (t & 1) x ^= 0x1800u;
        if (t & 2) x ^= 0x1000u;
        if (t & 4) x ^= 0x600u;
        if (t & 8) x ^= 0x400u;
        ld2(sbase + (obase ^ swaddr(x)), Re[t], Im[t]);
    }
    apply_gates2<4, 6>(Re, Im, combos, tg);
#pragma unroll
    for (int t = 0; t < 16; ++t) {
        uint32_t x = 0;
        if (t & 1) x ^= 0x1800u;
        if (t & 2) x ^= 0x1000u;
        if (t & 4) x ^= 0x600u;
        if (t & 8) x ^= 0x400u;
        st2(sbase + (obase ^ swaddr(x)), Re[t], Im[t]);
    }
}

// Pass D: XX(5,6) + RX q5,q6 (lane-uniform) + packed |amp|^2 + permuted scatter.
__device__ __forceinline__ void run_passD(Smem* sm, uint32_t sbase) {
    constexpr int combos[3] = {1, 2, 3};
    constexpr int slots[3]  = {2, 12, 13};
    constexpr int XT[4] = {0, 0x180, 0x100, 0x080};
    float tg[3];
#pragma unroll
    for (int g = 0; g < 3; ++g) tg[g] = sm->ps[slots[g]];
#pragma unroll
    for (int it = 0; it < 4; ++it) {
        const int kp = threadIdx.x + it * NT;
        const int rep = ((kp << 1) & 0x7F) | ((kp >> 6) << 9);   // bit0 = 0
        const uint32_t obase = swaddr((uint32_t)rep);
        u64 Re[4], Im[4];
#pragma unroll
        for (int t = 0; t < 4; ++t)
            ld2(sbase + (obase ^ swaddr((uint32_t)XT[t])), Re[t], Im[t]);
        apply_gates2<2, 3>(Re, Im, combos, tg);
#pragma unroll
        for (int t = 0; t < 4; ++t) {
            const u64 prP = fma2(Re[t], Re[t], mul2(Im[t], Im[t]));
            float p0, p1; unpack2(prP, p0, p1);
            sm->pbuf[(int)g_inv_tab.v[rep ^ XT[t]]]     = p0;   // table is pre-swizzled
            sm->pbuf[(int)g_inv_tab.v[rep ^ XT[t] ^ 1]] = p1;
        }
    }
}

// Pass E: Walsh-style sign-tree reduction; de-swizzled conflict-free loads.
__device__ __forceinline__ void run_passE(Smem* sm, float (&acc)[NQ]) {
    const int tid = threadIdx.x;
    const int c2 = tid & 7;                       // pbuf bank-swizzle constant
    float pv[32];
#pragma unroll
    for (int q = 0; q < 8; ++q) {
        const float4 v = reinterpret_cast<const float4*>(sm->pbuf)[tid * 8 + (q ^ c2)];
        pv[4 * q + 0] = v.x; pv[4 * q + 1] = v.y; pv[4 * q + 2] = v.z; pv[4 * q + 3] = v.w;
    }
    float D0 = 0.f, D1 = 0.f, D2 = 0.f, D3 = 0.f;
    float s16[16];
#pragma unroll
    for (int i = 0; i < 16; ++i) { s16[i] = pv[2*i] + pv[2*i+1]; D0 += pv[2*i] - pv[2*i+1]; }
    float s8[8];
#pragma unroll
    for (int i = 0; i < 8; ++i)  { s8[i] = s16[2*i] + s16[2*i+1]; D1 += s16[2*i] - s16[2*i+1]; }
    float s4[4];
#pragma unroll
    for (int i = 0; i < 4; ++i)  { s4[i] = s8[2*i] + s8[2*i+1]; D2 += s8[2*i] - s8[2*i+1]; }
    float s2a[2];
#pragma unroll
    for (int i = 0; i < 2; ++i)  { s2a[i] = s4[2*i] + s4[2*i+1]; D3 += s4[2*i] - s4[2*i+1]; }
    const float S  = s2a[0] + s2a[1];
    const float D4 = s2a[0] - s2a[1];
    acc[13] = D0; acc[12] = D1; acc[11] = D2; acc[10] = D3; acc[9] = D4;
#pragma unroll
    for (int bb = 5; bb <= 13; ++bb)
        acc[13 - bb] = ((tid >> (bb - 5)) & 1) ? -S : S;
}

__global__ __launch_bounds__(NT, 1)
void qsim_kernel(const float* __restrict__ cp, const float* __restrict__ p,
                 float* __restrict__ out) {
    extern __shared__ char smraw[];
    Smem* sm = reinterpret_cast<Smem*>(smraw);
    const int tid = threadIdx.x;
    const int b = blockIdx.x;
    const uint32_t sbase = smem_u32(sm->st);

    if (tid < NQ) {
        const int w = tid;
        float sn, cs;
        if (w >= 7) {
            sincosf(0.5f * cp[b * NQ + w], &sn, &cs);
            sm->pc[w - 7] = cs; sm->ps[w - 7] = sn / cs;   // cos + tangent
        }
        sincosf(0.5f * p[(b * 3 + 2) * NQ + w], &sn, &cs);
        sm->pc[7 + w] = cs; sm->ps[7 + w] = sn / cs;
    }
    // Pair tables: T_m for bit-pair (2m+1, 2m) = qubit pair (2k, 2k+1), k = 6-m.
    if (tid < 7) {
        const int m = tid, k = 6 - m;
        const int qa = 2 * k, qb = 2 * k + 1;
        float sa, ca, sb, cb, sx, cx;
        sincosf(0.5f * p[(b * 3 + 0) * NQ + qa], &sa, &ca);
        sincosf(0.5f * p[(b * 3 + 0) * NQ + qb], &sb, &cb);
        sincosf(0.5f * cp[b * NQ + k], &sx, &cx);
        float2 v[4] = { make_float2(ca * cb, 0.f), make_float2(0.f, -ca * sb),
                        make_float2(0.f, -sa * cb), make_float2(-sa * sb, 0.f) };
        float2 u[4];
#pragma unroll
        for (int j = 0; j < 4; ++j) {
            const float2 pv = v[j], qv = v[j ^ 3];
            u[j] = make_float2(fmaf(cx, pv.x,  sx * qv.y), fmaf(cx, pv.y, -sx * qv.x));
        }
        const float tza = p[(b * 3 + 1) * NQ + qa];
        const float tzb = p[(b * 3 + 1) * NQ + qb];
#pragma unroll
        for (int j = 0; j < 4; ++j) {
            const float ang = 0.5f * (((j & 2) ? tza : -tza) + ((j & 1) ? tzb : -tzb));
            float se, ce;
            sincosf(ang, &se, &ce);
            sm->T[m][j] = cmul(u[j], make_float2(ce, se));
        }
    }
    __syncthreads();

    run_passA(sm, sbase);
    __syncthreads();
    run_passB(sm, sbase);
    __syncthreads();
    run_passC(sm, sbase);
    __syncthreads();
    run_passD(sm, sbase);
    __syncthreads();

    float acc[NQ];
    run_passE(sm, acc);

#pragma unroll
    for (int w = 0; w < NQ; ++w)
#pragma unroll
        for (int off = 16; off > 0; off >>= 1)
            acc[w] += __shfl_xor_sync(0xffffffffu, acc[w], off);

    const int warp = tid >> 5, lane = tid & 31;
    if (lane == 0) {
#pragma unroll
        for (int w = 0; w < NQ; ++w) sm->red[warp * NQ + w] = acc[w];
    }
    __syncthreads();
    if (tid < NQ) {
        float s = 0.f;
#pragma unroll
        for (int ww = 0; ww < NT / 32; ++ww) s += sm->red[ww * NQ + tid];
        out[b * NQ + tid] = s;
    }
}

} // namespace

extern "C" void kernel_launch(void* const* d_in, const int* in_sizes, int n_in,
                              void* d_out, int out_size) {
    const float* cp = (const float*)d_in[0];
    const float* p  = (const float*)d_in[1];
    float* out = (float*)d_out;
    const int B = in_sizes[0] / NQ;   // 512
    cudaFuncSetAttribute(qsim_kernel, cudaFuncAttributeMaxDynamicSharedMemorySize,
                         (int)sizeof(Smem));
    qsim_kernel<<<B, NT, sizeof(Smem)>>>(cp, p, out);
}

// round 16
// speedup vs baseline: 1.6580x; 1.0991x over previous
#include <cuda_runtime.h>
#include <stdint.h>

namespace {
typedef unsigned long long u64;

constexpr int NQ = 14;
constexpr int NS = 1 << NQ;          // 16384 amplitudes
constexpr int NT = 512;              // threads per CTA

struct Smem {
    float2 st[NS];                    // state; block layout [r0 r1 i0 i1] per (i,i^1) pair
    float  pbuf[NS];                  // permuted probabilities (bank-swizzled layout)
    float2 T[7][4];                   // pair tables (T[0],T[6] are temps for T4)
    float2 T4[16];                    // 4-bit table over bits {13,12,1,0} incl. folded gates
    float pc[21], ps[21];             // per gate slot: pc = cos, ps = tan
    float red[(NT / 32) * NQ];
};

// Compile-time inverse of the composed MCX permutation, pre-composed with the
// pbuf bank swizzle phys = i ^ (((i>>5)&7)<<2).
struct alignas(4) InvTab { uint16_t v[NS]; };
__host__ __device__ constexpr InvTab make_inv() {
    InvTab t{};
    for (int i = 0; i < NS; ++i) {
        int j = i;
        for (int w = NQ - 1; w >= 0; --w) {
            const int c1 = NQ - 1 - w;
            const int c2 = NQ - 1 - ((w + 1) % NQ);
            const int tt = NQ - 1 - ((w + 2) % NQ);
            const int b1 = (j >> c1) & 1;
            const int b2 = (j >> c2) & 1;
            if (b1 & (b2 ^ 1)) j ^= (1 << tt);
        }
        t.v[j] = (uint16_t)(i ^ (((i >> 5) & 7) << 2));
    }
    return t;
}
__device__ constexpr InvTab g_inv_tab = make_inv();

// ---- packed f32x2 helpers ----
__device__ __forceinline__ u64 pack2(float lo, float hi) {
    u64 r; asm("mov.b64 %0, {%1, %2};" : "=l"(r) : "f"(lo), "f"(hi)); return r;
}
__device__ __forceinline__ void unpack2(u64 v, float& lo, float& hi) {
    asm("mov.b64 {%0, %1}, %2;" : "=f"(lo), "=f"(hi) : "l"(v));
}
__device__ __forceinline__ u64 bcast2(float x) { return pack2(x, x); }
__device__ __forceinline__ u64 fma2(u64 a, u64 b, u64 c) {
    u64 d; asm("fma.rn.f32x2 %0, %1, %2, %3;" : "=l"(d) : "l"(a), "l"(b), "l"(c)); return d;
}
__device__ __forceinline__ u64 mul2(u64 a, u64 b) {
    u64 d; asm("mul.rn.f32x2 %0, %1, %2;" : "=l"(d) : "l"(a), "l"(b)); return d;
}

__device__ __forceinline__ float2 cmul(float2 a, float2 b) {
    return make_float2(fmaf(a.x, b.x, -a.y * b.y), fmaf(a.x, b.y, a.y * b.x));
}

__device__ __forceinline__ uint32_t smem_u32(const void* p) {
    uint32_t r;
    asm("{ .reg .u64 t; cvta.to.shared.u64 t, %1; cvt.u32.u64 %0, t; }" : "=r"(r) : "l"(p));
    return r;
}

// XOR-linear swizzle; index bit0 -> addr bit3 ONLY, so (i, i^1) is one aligned 16B block.
__device__ __host__ __forceinline__ uint32_t swaddr(uint32_t i) {
    return (i << 3) ^ ((i >> 1) & 0x70u);
}

// Zero-mov packed pair access: block = [r0 r1 i0 i1] -> R = (r0,r1), I = (i0,i1)
__device__ __forceinline__ void ld2(uint32_t addr, u64& R, u64& I) {
    asm volatile("ld.shared.v2.b64 {%0, %1}, [%2];" : "=l"(R), "=l"(I) : "r"(addr));
}
__device__ __forceinline__ void st2(uint32_t addr, u64 R, u64 I) {
    asm volatile("st.shared.v2.b64 [%0], {%1, %2};" :: "r"(addr), "l"(R), "l"(I) : "memory");
}

// Tangent-form lane-uniform butterflies: one fma2 per element update.
template<int G, int NG>
__device__ __forceinline__ void apply_gates2(u64 (&Re)[1 << G], u64 (&Im)[1 << G],
                                             const int (&combos)[NG], const float (&tg)[NG]) {
#pragma unroll
    for (int g = 0; g < NG; ++g) {
        const int cb = combos[g], lb = cb & (-cb);
        const u64 tP = bcast2(tg[g]), ntP = bcast2(-tg[g]);
#pragma unroll
        for (int t = 0; t < (1 << G); ++t) {
            if ((t & lb) == 0) {
                const int u = t ^ cb;
                const u64 r0 = fma2(tP,  Im[u], Re[t]);
                const u64 i0 = fma2(ntP, Re[u], Im[t]);
                const u64 r1 = fma2(tP,  Im[t], Re[u]);
                const u64 i1 = fma2(ntP, Re[t], Im[u]);
                Re[t] = r0; Im[t] = i0; Re[u] = r1; Im[u] = i1;
            }
        }
    }
}

// Pass A: generate packed state (scaled by P = prod of the 18 tan-gate cosines)
// + tan-form XX(9,10),(11,12),RX q9-12.
__device__ __forceinline__ void run_passA(Smem* sm, uint32_t sbase) {
    constexpr int combos[6] = {1, 4, 2, 3, 8, 12};
    constexpr int slots[6]  = {4, 5, 16, 17, 18, 19};
    float tg[6];
#pragma unroll
    for (int g = 0; g < 6; ++g) tg[g] = sm->ps[slots[g]];

    // cosine product over tan-form gates (folded slots 6, 7, 20 excluded)
    float P = (sm->pc[0] * sm->pc[1]) * (sm->pc[2] * sm->pc[3]) * (sm->pc[4] * sm->pc[5]);
    P *= ((sm->pc[8] * sm->pc[9]) * (sm->pc[10] * sm->pc[11])) *
         ((sm->pc[12] * sm->pc[13]) * (sm->pc[14] * sm->pc[15]));
    P *= (sm->pc[16] * sm->pc[17]) * (sm->pc[18] * sm->pc[19]);

    const int tid = threadIdx.x;                // exactly 512 orbit-pairs
    const int rep = tid << 5;                   // bits 5-13 = tid bits 0-8; bit0 = 0
    const uint32_t obase = swaddr((uint32_t)rep);
    float2 base = cmul(cmul(sm->T[3][(rep >> 6) & 3], sm->T[4][(rep >> 8) & 3]),
                       sm->T[5][(rep >> 10) & 3]);
    base.x *= P; base.y *= P;
    const int b5 = tid & 1;
    const float2 q2x[2] = { cmul(base, sm->T[2][2 * b5]),
                            cmul(base, sm->T[2][1 + 2 * b5]) };      // index = bit4
    float2 m8[2][4];
#pragma unroll
    for (int b4 = 0; b4 < 2; ++b4)
#pragma unroll
        for (int j23 = 0; j23 < 4; ++j23)
            m8[b4][j23] = cmul(q2x[b4], sm->T[1][j23]);
    // packed T4 lanes: group selected by state bits 13,12; entry bit1, lane = bit0
    const int hi = ((rep >> 12) & 3) << 2;
    u64 T0re[2], T0im[2];
#pragma unroll
    for (int b1 = 0; b1 < 2; ++b1) {
        T0re[b1] = pack2(sm->T4[hi + 2 * b1].x, sm->T4[hi + 2 * b1 + 1].x);
        T0im[b1] = pack2(sm->T4[hi + 2 * b1].y, sm->T4[hi + 2 * b1 + 1].y);
    }
    u64 Re[16], Im[16];
#pragma unroll
    for (int t = 0; t < 16; ++t) {
        const int t0 = t & 1, t1 = (t >> 1) & 1, t2 = (t >> 2) & 1, t3 = (t >> 3) & 1;
        const float2 m = m8[t0 ^ t1][(t0 << 1) | (t2 ^ t3)];
        const u64 mx = bcast2(m.x), my = bcast2(m.y), nmy = bcast2(-m.y);
        Re[t] = fma2(mx, T0re[t2], mul2(nmy, T0im[t2]));
        Im[t] = fma2(mx, T0im[t2], mul2(my,  T0re[t2]));
    }
    apply_gates2<4, 6>(Re, Im, combos, tg);
#pragma unroll
    for (int t = 0; t < 16; ++t) {
        uint32_t x = 0;
        if (t & 1) x ^= 0x18u;
        if (t & 2) x ^= 0x10u;
        if (t & 4) x ^= 0x06u;
        if (t & 8) x ^= 0x04u;
        st2(sbase + (obase ^ swaddr(x)), Re[t], Im[t]);
    }
}

// Pass C: XX(1,2), RX q1,q2, XX(3,4), RX q3,q4 — fully lane-uniform.
__device__ __forceinline__ void run_passC(Smem* sm, uint32_t sbase) {
    constexpr int combos[6] = {1, 2, 3, 4, 8, 12};
    constexpr int slots[6]  = {0, 8, 9, 1, 10, 11};
    float tg[6];
#pragma unroll
    for (int g = 0; g < 6; ++g) tg[g] = sm->ps[slots[g]];
    const int tid = threadIdx.x;                   // 512 orbit-pairs
    const int rep = ((tid << 1) & 0x1FF) | ((tid >> 8) << 13);   // bit0 = 0
    const uint32_t obase = swaddr((uint32_t)rep);
    u64 Re[16], Im[16];
#pragma unroll
    for (int t = 0; t < 16; ++t) {
        uint32_t x = 0;
        if (t & 1) x ^= 0x1800u;
        if (t & 2) x ^= 0x1000u;
        if (t & 4) x ^= 0x600u;
        if (t & 8) x ^= 0x400u;
        ld2(sbase + (obase ^ swaddr(x)), Re[t], Im[t]);
    }
    apply_gates2<4, 6>(Re, Im, combos, tg);
#pragma unroll
    for (int t = 0; t < 16; ++t) {
        uint32_t x = 0;
        if (t & 1) x ^= 0x1800u;
        if (t & 2) x ^= 0x1000u;
        if (t & 4) x ^= 0x600u;
        if (t & 8) x ^= 0x400u;
        st2(sbase + (obase ^ swaddr(x)), Re[t], Im[t]);
    }
}

// Pass BD: XX(5,6),RXq5,q6, XX(7,8),RXq7,q8 + packed |amp|^2 + permuted scatter.
__device__ __forceinline__ void run_passBD(Smem* sm, uint32_t sbase) {
    constexpr int combos[6] = {1, 2, 3, 4, 8, 12};   // masks over gens below
    constexpr int slots[6]  = {2, 12, 13, 3, 14, 15};
    float tg[6];
#pragma unroll
    for (int g = 0; g < 6; ++g) tg[g] = sm->ps[slots[g]];
    const int tid = threadIdx.x;                   // 512 orbit-pairs, span bits 5-8
    const int rep = ((tid & 0xF) << 1) | ((tid >> 4) << 9);   // bits 1-4, 9-13; bit0=0
    const uint32_t obase = swaddr((uint32_t)rep);
    u64 Re[16], Im[16];
#pragma unroll
    for (int t = 0; t < 16; ++t) {
        uint32_t x = 0;
        if (t & 1) x ^= 0x180u;
        if (t & 2) x ^= 0x100u;
        if (t & 4) x ^= 0x60u;
        if (t & 8) x ^= 0x40u;
        ld2(sbase + (obase ^ swaddr(x)), Re[t], Im[t]);
    }
    apply_gates2<4, 6>(Re, Im, combos, tg);
#pragma unroll
    for (int t = 0; t < 16; ++t) {
        uint32_t x = 0;
        if (t & 1) x ^= 0x180u;
        if (t & 2) x ^= 0x100u;
        if (t & 4) x ^= 0x60u;
        if (t & 8) x ^= 0x40u;
        const u64 prP = fma2(Re[t], Re[t], mul2(Im[t], Im[t]));
        float p0, p1; unpack2(prP, p0, p1);
        const int i0 = rep ^ (int)x;               // even index
        const uint32_t pair =
            __ldg(reinterpret_cast<const uint32_t*>(g_inv_tab.v + i0));
        sm->pbuf[pair & 0xFFFFu] = p0;             // target of i0 (bit0 = 0 lane)
        sm->pbuf[pair >> 16]     = p1;             // target of i0^1
    }
}

// Pass E: Walsh-style sign-tree reduction; de-swizzled conflict-free loads.
__device__ __forceinline__ void run_passE(Smem* sm, float (&acc)[NQ]) {
    const int tid = threadIdx.x;
    const int c2 = tid & 7;                       // pbuf bank-swizzle constant
    float pv[32];
#pragma unroll
    for (int q = 0; q < 8; ++q) {
        const float4 v = reinterpret_cast<const float4*>(sm->pbuf)[tid * 8 + (q ^ c2)];
        pv[4 * q + 0] = v.x; pv[4 * q + 1] = v.y; pv[4 * q + 2] = v.z; pv[4 * q + 3] = v.w;
    }
    float D0 = 0.f, D1 = 0.f, D2 = 0.f, D3 = 0.f;
    float s16[16];
#pragma unroll
    for (int i = 0; i < 16; ++i) { s16[i] = pv[2*i] + pv[2*i+1]; D0 += pv[2*i] - pv[2*i+1]; }
    float s8[8];
#pragma unroll
    for (int i = 0; i < 8; ++i)  { s8[i] = s16[2*i] + s16[2*i+1]; D1 += s16[2*i] - s16[2*i+1]; }
    float s4[4];
#pragma unroll
    for (int i = 0; i < 4; ++i)  { s4[i] = s8[2*i] + s8[2*i+1]; D2 += s8[2*i] - s8[2*i+1]; }
    float s2a[2];
#pragma unroll
    for (int i = 0; i < 2; ++i)  { s2a[i] = s4[2*i] + s4[2*i+1]; D3 += s4[2*i] - s4[2*i+1]; }
    const float S  = s2a[0] + s2a[1];
    const float D4 = s2a[0] - s2a[1];
    acc[13] = D0; acc[12] = D1; acc[11] = D2; acc[10] = D3; acc[9] = D4;
#pragma unroll
    for (int bb = 5; bb <= 13; ++bb)
        acc[13 - bb] = ((tid >> (bb - 5)) & 1) ? -S : S;
}

__global__ __launch_bounds__(NT, 1)
void qsim_kernel(const float* __restrict__ cp, const float* __restrict__ p,
                 float* __restrict__ out) {
    extern __shared__ char smraw[];
    Smem* sm = reinterpret_cast<Smem*>(smraw);
    const int tid = threadIdx.x;
    const int b = blockIdx.x;
    const uint32_t sbase = smem_u32(sm->st);

    // Phase 1a: gate coefficients (cos + tan). Slots 6,7,20 feed the T4 fold.
    if (tid < NQ) {
        const int w = tid;
        float sn, cs;
        if (w >= 7) {
            sincosf(0.5f * cp[b * NQ + w], &sn, &cs);
            sm->pc[w - 7] = cs; sm->ps[w - 7] = sn / cs;
        }
        sincosf(0.5f * p[(b * 3 + 2) * NQ + w], &sn, &cs);
        sm->pc[7 + w] = cs; sm->ps[7 + w] = sn / cs;
    }
    // Phase 1b (threads 14-20): pair tables T_m for bit-pair (2m+1,2m) = qubits (2k,2k+1), k=6-m.
    if (tid >= 14 && tid < 21) {
        const int m = tid - 14, k = 6 - m;
        const int qa = 2 * k, qb = 2 * k + 1;
        float sa, ca, sb, cb, sx, cx;
        sincosf(0.5f * p[(b * 3 + 0) * NQ + qa], &sa, &ca);
        sincosf(0.5f * p[(b * 3 + 0) * NQ + qb], &sb, &cb);
        sincosf(0.5f * cp[b * NQ + k], &sx, &cx);
        float2 v[4] = { make_float2(ca * cb, 0.f), make_float2(0.f, -ca * sb),
                        make_float2(0.f, -sa * cb), make_float2(-sa * sb, 0.f) };
        float2 u[4];
#pragma unroll
        for (int j = 0; j < 4; ++j) {
            const float2 pv = v[j], qv = v[j ^ 3];
            u[j] = make_float2(fmaf(cx, pv.x,  sx * qv.y), fmaf(cx, pv.y, -sx * qv.x));
        }
        const float tza = p[(b * 3 + 1) * NQ + qa];
        const float tzb = p[(b * 3 + 1) * NQ + qb];
#pragma unroll
        for (int j = 0; j < 4; ++j) {
            const float ang = 0.5f * (((j & 2) ? tza : -tza) + ((j & 1) ? tzb : -tzb));
            float se, ce;
            sincosf(ang, &se, &ce);
            sm->T[m][j] = cmul(u[j], make_float2(ce, se));
        }
    }
    __syncthreads();

    // Phase 2: fold XX(13,0), RX q0, RX q13 exactly into T4 over bits {13,12,1,0}.
    // T4[j] depends only on v at {j, j^1, j^8, j^9}.
    if (tid < 16) {
        const int j = tid;
        const float cx  = sm->pc[6],  sx  = sm->ps[6]  * sm->pc[6];
        const float c7  = sm->pc[7],  s7  = sm->ps[7]  * sm->pc[7];
        const float c20 = sm->pc[20], s20 = sm->ps[20] * sm->pc[20];
        const int idx[4] = {j, j ^ 1, j ^ 8, j ^ 9};
        float2 v[4], w[4];
#pragma unroll
        for (int a = 0; a < 4; ++a)
            v[a] = cmul(sm->T[6][idx[a] >> 2], sm->T[0][idx[a] & 3]);
        // XX(13,0): partner mask 9 -> within group a^3
#pragma unroll
        for (int a = 0; a < 4; ++a) {
            const float2 pv = v[a], qv = v[a ^ 3];
            w[a] = make_float2(fmaf(cx, pv.x,  sx * qv.y), fmaf(cx, pv.y, -sx * qv.x));
        }
        // RX q0 (mask 8 -> a^2), needed at a=0,1
        float2 uu[2];
#pragma unroll
        for (int a = 0; a < 2; ++a)
            uu[a] = make_float2(fmaf(c7, w[a].x,  s7 * w[a ^ 2].y),
                                fmaf(c7, w[a].y, -s7 * w[a ^ 2].x));
        // RX q13 (mask 1 -> a^1), final at a=0
        sm->T4[j] = make_float2(fmaf(c20, uu[0].x,  s20 * uu[1].y),
                                fmaf(c20, uu[0].y, -s20 * uu[1].x));
    }
    __syncthreads();

    run_passA(sm, sbase);
    __syncthreads();
    run_passC(sm, sbase);
    __syncthreads();
    run_passBD(sm, sbase);
    __syncthreads();

    float acc[NQ];
    run_passE(sm, acc);

#pragma unroll
    for (int w = 0; w < NQ; ++w)
#pragma unroll
        for (int off = 16; off > 0; off >>= 1)
            acc[w] += __shfl_xor_sync(0xffffffffu, acc[w], off);

    const int warp = tid >> 5, lane = tid & 31;
    if (lane == 0) {
#pragma unroll
        for (int w = 0; w < NQ; ++w) sm->red[warp * NQ + w] = acc[w];
    }
    __syncthreads();
    if (tid < NQ) {
        float s = 0.f;
#pragma unroll
        for (int ww = 0; ww < NT / 32; ++ww) s += sm->red[ww * NQ + tid];
        out[b * NQ + tid] = s;
    }
}

} // namespace

extern "C" void kernel_launch(void* const* d_in, const int* in_sizes, int n_in,
                              void* d_out, int out_size) {
    const float* cp = (const float*)d_in[0];
    const float* p  = (const float*)d_in[1];
    float* out = (float*)d_out;
    const int B = in_sizes[0] / NQ;   // 512
    cudaFuncSetAttribute(qsim_kernel, cudaFuncAttributeMaxDynamicSharedMemorySize,
                         (int)sizeof(Smem));
    qsim_kernel<<<B, NT, sizeof(Smem)>>>(cp, p, out);
}

// round 17
// speedup vs baseline: 1.8354x; 1.1070x over previous
#include <cuda_runtime.h>
#include <stdint.h>

namespace {
typedef unsigned long long u64;

constexpr int NQ = 14;
constexpr int NS = 1 << NQ;          // 16384 amplitudes
constexpr int NT = 512;              // threads per CTA

struct Smem {
    float2 st[NS];                    // state; block layout [r0 r1 i0 i1] per (i,i^1) pair
    float  pbuf[NS];                  // permuted probabilities (bank-swizzled layout)
    float2 T[7][4];                   // pair tables: prefix circuit per bit-pair
    float2 B8[256];                   // 8-bit table over state bits {13,12,5,4,3,2,1,0}
    float pc[21], ps[21];             // per gate slot: pc = cos, ps = tan
    float red[(NT / 32) * NQ];
};

// Compile-time inverse of the composed MCX permutation, pre-composed with the
// pbuf bank swizzle phys = i ^ (((i>>5)&7)<<2).
struct alignas(4) InvTab { uint16_t v[NS]; };
__host__ __device__ constexpr InvTab make_inv() {
    InvTab t{};
    for (int i = 0; i < NS; ++i) {
        int j = i;
        for (int w = NQ - 1; w >= 0; --w) {
            const int c1 = NQ - 1 - w;
            const int c2 = NQ - 1 - ((w + 1) % NQ);
            const int tt = NQ - 1 - ((w + 2) % NQ);
            const int b1 = (j >> c1) & 1;
            const int b2 = (j >> c2) & 1;
            if (b1 & (b2 ^ 1)) j ^= (1 << tt);
        }
        t.v[j] = (uint16_t)(i ^ (((i >> 5) & 7) << 2));
    }
    return t;
}
__device__ constexpr InvTab g_inv_tab = make_inv();

// ---- packed f32x2 helpers ----
__device__ __forceinline__ u64 pack2(float lo, float hi) {
    u64 r; asm("mov.b64 %0, {%1, %2};" : "=l"(r) : "f"(lo), "f"(hi)); return r;
}
__device__ __forceinline__ void unpack2(u64 v, float& lo, float& hi) {
    asm("mov.b64 {%0, %1}, %2;" : "=f"(lo), "=f"(hi) : "l"(v));
}
__device__ __forceinline__ u64 bcast2(float x) { return pack2(x, x); }
__device__ __forceinline__ u64 fma2(u64 a, u64 b, u64 c) {
    u64 d; asm("fma.rn.f32x2 %0, %1, %2, %3;" : "=l"(d) : "l"(a), "l"(b), "l"(c)); return d;
}
__device__ __forceinline__ u64 mul2(u64 a, u64 b) {
    u64 d; asm("mul.rn.f32x2 %0, %1, %2;" : "=l"(d) : "l"(a), "l"(b)); return d;
}

__device__ __forceinline__ float2 cmul(float2 a, float2 b) {
    return make_float2(fmaf(a.x, b.x, -a.y * b.y), fmaf(a.x, b.y, a.y * b.x));
}

__device__ __forceinline__ uint32_t smem_u32(const void* p) {
    uint32_t r;
    asm("{ .reg .u64 t; cvta.to.shared.u64 t, %1; cvt.u32.u64 %0, t; }" : "=r"(r) : "l"(p));
    return r;
}

// XOR-linear swizzle; index bit0 -> addr bit3 ONLY, so (i, i^1) is one aligned 16B block.
__device__ __host__ __forceinline__ uint32_t swaddr(uint32_t i) {
    return (i << 3) ^ ((i >> 1) & 0x70u);
}

// Zero-mov packed pair access: block = [r0 r1 i0 i1] -> R = (r0,r1), I = (i0,i1)
__device__ __forceinline__ void ld2(uint32_t addr, u64& R, u64& I) {
    asm volatile("ld.shared.v2.b64 {%0, %1}, [%2];" : "=l"(R), "=l"(I) : "r"(addr));
}
__device__ __forceinline__ void st2(uint32_t addr, u64 R, u64 I) {
    asm volatile("st.shared.v2.b64 [%0], {%1, %2};" :: "r"(addr), "l"(R), "l"(I) : "memory");
}

// Tangent-form lane-uniform butterflies: one fma2 per element update.
template<int G, int NG>
__device__ __forceinline__ void apply_gates2(u64 (&Re)[1 << G], u64 (&Im)[1 << G],
                                             const int (&combos)[NG], const float (&tg)[NG]) {
#pragma unroll
    for (int g = 0; g < NG; ++g) {
        const int cb = combos[g], lb = cb & (-cb);
        const u64 tP = bcast2(tg[g]), ntP = bcast2(-tg[g]);
#pragma unroll
        for (int t = 0; t < (1 << G); ++t) {
            if ((t & lb) == 0) {
                const int u = t ^ cb;
                const u64 r0 = fma2(tP,  Im[u], Re[t]);
                const u64 i0 = fma2(ntP, Re[u], Im[t]);
                const u64 r1 = fma2(tP,  Im[t], Re[u]);
                const u64 i1 = fma2(ntP, Re[t], Im[u]);
                Re[t] = r0; Im[t] = i0; Re[u] = r1; Im[u] = i1;
            }
        }
    }
}

// Pass 1: generate packed state from B8 (x) T3 (x) T4 (x) T5 and apply
// XX(1,2),RXq1,q2, XX(3,4),RXq3,q4 (span dims 9-12), then store.
__device__ __forceinline__ void run_pass1(Smem* sm, uint32_t sbase) {
    constexpr int combos[6] = {1, 2, 3, 4, 8, 12};
    constexpr int slots[6]  = {0, 8, 9, 1, 10, 11};
    float tg[6];
#pragma unroll
    for (int g = 0; g < 6; ++g) tg[g] = sm->ps[slots[g]];

    const int tid = threadIdx.x;                   // 512 orbits, span bits 9-12
    const int rep = ((tid << 1) & 0x1FF) | ((tid >> 8) << 13);   // bits 1-8, 13; bit0=0
    const uint32_t obase = swaddr((uint32_t)rep);

    // B8 packed pairs: idx = (state bits 5..0) | (bit12<<6) | (bit13<<7); lanes = bit0
    const int ib = (rep & 0x3F) | ((rep >> 6) & 0x80);           // bit6 (b12) varies by orbit
    const float4 v0 = *reinterpret_cast<const float4*>(&sm->B8[ib]);         // b12 = 0
    const float4 v1 = *reinterpret_cast<const float4*>(&sm->B8[ib ^ 0x40]);  // b12 = 1
    u64 BR[2] = { pack2(v0.x, v0.z), pack2(v1.x, v1.z) };
    u64 BI[2] = { pack2(v0.y, v0.w), pack2(v1.y, v1.w) };

    // lane-uniform factor tree: T3 (bits 6,7 fixed), T4 (bit8 fixed, bit9 = b9), T5 (b10,b11)
    const float2 t3c = sm->T[3][(rep >> 6) & 3];
    const int b8f = (rep >> 8) & 1;
    const float2 t40 = cmul(t3c, sm->T[4][b8f]);       // b9 = 0
    const float2 t41 = cmul(t3c, sm->T[4][2 | b8f]);   // b9 = 1
    float2 M[2][4];
#pragma unroll
    for (int k = 0; k < 4; ++k) {
        M[0][k] = cmul(t40, sm->T[5][k]);
        M[1][k] = cmul(t41, sm->T[5][k]);
    }

    // element t over gens {0x1800,0x1000,0x600,0x400}: b12=t0^t1, b11=t0, b10=t2^t3, b9=t2
    u64 Re[16], Im[16];
#pragma unroll
    for (int t = 0; t < 16; ++t) {
        const int t0 = t & 1, t1 = (t >> 1) & 1, t2 = (t >> 2) & 1, t3b = (t >> 3) & 1;
        const float2 m = M[t2][(t0 << 1) | (t2 ^ t3b)];
        const int b12 = t0 ^ t1;
        const u64 mx = bcast2(m.x), my = bcast2(m.y), nmy = bcast2(-m.y);
        Re[t] = fma2(mx, BR[b12], mul2(nmy, BI[b12]));
        Im[t] = fma2(mx, BI[b12], mul2(my,  BR[b12]));
    }
    apply_gates2<4, 6>(Re, Im, combos, tg);
#pragma unroll
    for (int t = 0; t < 16; ++t) {
        uint32_t x = 0;
        if (t & 1) x ^= 0x1800u;
        if (t & 2) x ^= 0x1000u;
        if (t & 4) x ^= 0x600u;
        if (t & 8) x ^= 0x400u;
        st2(sbase + (obase ^ swaddr(x)), Re[t], Im[t]);
    }
}

// Pass BD: XX(5,6),RXq5,q6, XX(7,8),RXq7,q8 + packed |amp|^2 + permuted scatter.
__device__ __forceinline__ void run_passBD(Smem* sm, uint32_t sbase) {
    constexpr int combos[6] = {1, 2, 3, 4, 8, 12};
    constexpr int slots[6]  = {2, 12, 13, 3, 14, 15};
    float tg[6];
#pragma unroll
    for (int g = 0; g < 6; ++g) tg[g] = sm->ps[slots[g]];
    const int tid = threadIdx.x;                   // 512 orbits, span bits 5-8
    const int rep = ((tid & 0xF) << 1) | ((tid >> 4) << 9);   // bits 1-4, 9-13; bit0=0
    const uint32_t obase = swaddr((uint32_t)rep);
    u64 Re[16], Im[16];
#pragma unroll
    for (int t = 0; t < 16; ++t) {
        uint32_t x = 0;
        if (t & 1) x ^= 0x180u;
        if (t & 2) x ^= 0x100u;
        if (t & 4) x ^= 0x60u;
        if (t & 8) x ^= 0x40u;
        ld2(sbase + (obase ^ swaddr(x)), Re[t], Im[t]);
    }
    apply_gates2<4, 6>(Re, Im, combos, tg);
#pragma unroll
    for (int t = 0; t < 16; ++t) {
        uint32_t x = 0;
        if (t & 1) x ^= 0x180u;
        if (t & 2) x ^= 0x100u;
        if (t & 4) x ^= 0x60u;
        if (t & 8) x ^= 0x40u;
        const u64 prP = fma2(Re[t], Re[t], mul2(Im[t], Im[t]));
        float p0, p1; unpack2(prP, p0, p1);
        const int i0 = rep ^ (int)x;
        const uint32_t pair =
            __ldg(reinterpret_cast<const uint32_t*>(g_inv_tab.v + i0));
        sm->pbuf[pair & 0xFFFFu] = p0;
        sm->pbuf[pair >> 16]     = p1;
    }
}

// Pass E: Walsh-style sign-tree reduction; de-swizzled conflict-free loads.
__device__ __forceinline__ void run_passE(Smem* sm, float (&acc)[NQ]) {
    const int tid = threadIdx.x;
    const int c2 = tid & 7;
    float pv[32];
#pragma unroll
    for (int q = 0; q < 8; ++q) {
        const float4 v = reinterpret_cast<const float4*>(sm->pbuf)[tid * 8 + (q ^ c2)];
        pv[4 * q + 0] = v.x; pv[4 * q + 1] = v.y; pv[4 * q + 2] = v.z; pv[4 * q + 3] = v.w;
    }
    float D0 = 0.f, D1 = 0.f, D2 = 0.f, D3 = 0.f;
    float s16[16];
#pragma unroll
    for (int i = 0; i < 16; ++i) { s16[i] = pv[2*i] + pv[2*i+1]; D0 += pv[2*i] - pv[2*i+1]; }
    float s8[8];
#pragma unroll
    for (int i = 0; i < 8; ++i)  { s8[i] = s16[2*i] + s16[2*i+1]; D1 += s16[2*i] - s16[2*i+1]; }
    float s4[4];
#pragma unroll
    for (int i = 0; i < 4; ++i)  { s4[i] = s8[2*i] + s8[2*i+1]; D2 += s8[2*i] - s8[2*i+1]; }
    float s2a[2];
#pragma unroll
    for (int i = 0; i < 2; ++i)  { s2a[i] = s4[2*i] + s4[2*i+1]; D3 += s4[2*i] - s4[2*i+1]; }
    const float S  = s2a[0] + s2a[1];
    const float D4 = s2a[0] - s2a[1];
    acc[13] = D0; acc[12] = D1; acc[11] = D2; acc[10] = D3; acc[9] = D4;
#pragma unroll
    for (int bb = 5; bb <= 13; ++bb)
        acc[13 - bb] = ((tid >> (bb - 5)) & 1) ? -S : S;
}

__global__ __launch_bounds__(NT, 1)
void qsim_kernel(const float* __restrict__ cp, const float* __restrict__ p,
                 float* __restrict__ out) {
    extern __shared__ char smraw[];
    Smem* sm = reinterpret_cast<Smem*>(smraw);
    const int tid = threadIdx.x;
    const int b = blockIdx.x;
    const uint32_t sbase = smem_u32(sm->st);

    // Phase 1a: gate coefficients (cos + tan).
    if (tid < NQ) {
        const int w = tid;
        float sn, cs;
        if (w >= 7) {
            sincosf(0.5f * cp[b * NQ + w], &sn, &cs);
            sm->pc[w - 7] = cs; sm->ps[w - 7] = sn / cs;
        }
        sincosf(0.5f * p[(b * 3 + 2) * NQ + w], &sn, &cs);
        sm->pc[7 + w] = cs; sm->ps[7 + w] = sn / cs;
    }
    // Phase 1b (threads 14-20): pair tables T_m for bit-pair (2m+1,2m) = qubits (2k,2k+1), k=6-m.
    if (tid >= 14 && tid < 21) {
        const int m = tid - 14, k = 6 - m;
        const int qa = 2 * k, qb = 2 * k + 1;
        float sa, ca, sb, cb, sx, cx;
        sincosf(0.5f * p[(b * 3 + 0) * NQ + qa], &sa, &ca);
        sincosf(0.5f * p[(b * 3 + 0) * NQ + qb], &sb, &cb);
        sincosf(0.5f * cp[b * NQ + k], &sx, &cx);
        float2 v[4] = { make_float2(ca * cb, 0.f), make_float2(0.f, -ca * sb),
                        make_float2(0.f, -sa * cb), make_float2(-sa * sb, 0.f) };
        float2 u[4];
#pragma unroll
        for (int j = 0; j < 4; ++j) {
            const float2 pv = v[j], qv = v[j ^ 3];
            u[j] = make_float2(fmaf(cx, pv.x,  sx * qv.y), fmaf(cx, pv.y, -sx * qv.x));
        }
        const float tza = p[(b * 3 + 1) * NQ + qa];
        const float tzb = p[(b * 3 + 1) * NQ + qb];
#pragma unroll
        for (int j = 0; j < 4; ++j) {
            const float ang = 0.5f * (((j & 2) ? tza : -tza) + ((j & 1) ? tzb : -tzb));
            float se, ce;
            sincosf(ang, &se, &ce);
            sm->T[m][j] = cmul(u[j], make_float2(ce, se));
        }
    }
    __syncthreads();

    // Mini-fold M1 (16 threads): B8 over j bits {7..0} = state bits {13,12,5,4,3,2,1,0}.
    // v = T6 x T2 x T1 x T0; apply groups on state dims {0,13} and {1,2}
    // (j-masks: XX(13,0)=0x81->e9, RXq0=0x80->e8, RXq13=0x01->e1, XX(11,12)=0x06->e6,
    //  RXq11=0x04->e4, RXq12=0x02->e2). Orbit span = e dims {0,1,2,3(=j7)}.
    if (tid < 16) {
        const int jr = tid << 3;                   // j dims 3-6
        float2 v[16];
#pragma unroll
        for (int e = 0; e < 16; ++e) {
            const int j = jr ^ (e & 7) ^ ((e >> 3) << 7);
            v[e] = cmul(cmul(sm->T[6][(j >> 6) & 3], sm->T[2][(j >> 4) & 3]),
                        cmul(sm->T[1][(j >> 2) & 3], sm->T[0][j & 3]));
        }
        const int gm[6] = {9, 8, 1, 6, 4, 2};
        const int gs[6] = {6, 7, 20, 5, 18, 19};
#pragma unroll
        for (int g = 0; g < 6; ++g) {
            const float c = sm->pc[gs[g]], sn = sm->ps[gs[g]] * sm->pc[gs[g]];
            const int mm = gm[g], lb = mm & (-mm);
#pragma unroll
            for (int e = 0; e < 16; ++e) {
                if ((e & lb) == 0) {
                    const int u = e ^ mm;
                    const float2 a0 = v[e], a1 = v[u];
                    v[e] = make_float2(fmaf(c, a0.x,  sn * a1.y), fmaf(c, a0.y, -sn * a1.x));
                    v[u] = make_float2(fmaf(c, a1.x,  sn * a0.y), fmaf(c, a1.y, -sn * a0.x));
                }
            }
        }
#pragma unroll
        for (int e = 0; e < 16; ++e) {
            const int j = jr ^ (e & 7) ^ ((e >> 3) << 7);
            sm->B8[j] = v[e];
        }
    }
    __syncthreads();

    // Mini-fold M2 (64 threads): group on state dims {3,4} (j-masks 0x18,0x10,0x08 ->
    // f-masks 3,2,1), then scale by P = product of the 12 remaining gate cosines.
    if (tid < 64) {
        const int jr = (tid & 7) | ((tid >> 3) << 5);
        float2 v[4];
#pragma unroll
        for (int f = 0; f < 4; ++f) v[f] = sm->B8[jr ^ (f << 3)];
        const int gm[3] = {3, 2, 1};
        const int gs[3] = {4, 16, 17};
#pragma unroll
        for (int g = 0; g < 3; ++g) {
            const float c = sm->pc[gs[g]], sn = sm->ps[gs[g]] * sm->pc[gs[g]];
            const int mm = gm[g], lb = mm & (-mm);
#pragma unroll
            for (int f = 0; f < 4; ++f) {
                if ((f & lb) == 0) {
                    const int u = f ^ mm;
                    const float2 a0 = v[f], a1 = v[u];
                    v[f] = make_float2(fmaf(c, a0.x,  sn * a1.y), fmaf(c, a0.y, -sn * a1.x));
                    v[u] = make_float2(fmaf(c, a1.x,  sn * a0.y), fmaf(c, a1.y, -sn * a0.x));
                }
            }
        }
        float P = (sm->pc[0] * sm->pc[1]) * (sm->pc[2] * sm->pc[3]);
        P *= ((sm->pc[8] * sm->pc[9]) * (sm->pc[10] * sm->pc[11])) *
             ((sm->pc[12] * sm->pc[13]) * (sm->pc[14] * sm->pc[15]));
#pragma unroll
        for (int f = 0; f < 4; ++f) {
            v[f].x *= P; v[f].y *= P;
            sm->B8[jr ^ (f << 3)] = v[f];
        }
    }
    __syncthreads();

    run_pass1(sm, sbase);
    __syncthreads();
    run_passBD(sm, sbase);
    __syncthreads();

    float acc[NQ];
    run_passE(sm, acc);

#pragma unroll
    for (int w = 0; w < NQ; ++w)
#pragma unroll
        for (int off = 16; off > 0; off >>= 1)
            acc[w] += __shfl_xor_sync(0xffffffffu, acc[w], off);

    const int warp = tid >> 5, lane = tid & 31;
    if (lane == 0) {
#pragma unroll
        for (int w = 0; w < NQ; ++w) sm->red[warp * NQ + w] = acc[w];
    }
    __syncthreads();
    if (tid < NQ) {
        float s = 0.f;
#pragma unroll
        for (int ww = 0; ww < NT / 32; ++ww) s += sm->red[ww * NQ + tid];
        out[b * NQ + tid] = s;
    }
}

} // namespace

extern "C" void kernel_launch(void* const* d_in, const int* in_sizes, int n_in,
                              void* d_out, int out_size) {
    const float* cp = (const float*)d_in[0];
    const float* p  = (const float*)d_in[1];
    float* out = (float*)d_out;
    const int B = in_sizes[0] / NQ;   // 512
    cudaFuncSetAttribute(qsim_kernel, cudaFuncAttributeMaxDynamicSharedMemorySize,
                         (int)sizeof(Smem));
    qsim_kernel<<<B, NT, sizeof(Smem)>>>(cp, p, out);
}